// round 5
// baseline (speedup 1.0000x reference)
#include <cuda_runtime.h>
#include <math_constants.h>

#define BB 4
#define TT 2048
#define CC 768
#define HH 64
#define BQ 64
#define BK 64
#define NS 4   // kv splits

__device__ __align__(16) float g_q[BB * TT * HH];
__device__ __align__(16) float g_k[BB * TT * HH];
__device__ __align__(16) float g_v[BB * TT * HH];
__device__ __align__(16) float g_po[NS * BB * TT * HH];
__device__ float g_pm[NS * BB * TT];
__device__ float g_pl[NS * BB * TT];

typedef unsigned long long ull;

__device__ __forceinline__ void ffma2(ull& d, ull a, ull b) {
    asm("fma.rn.f32x2 %0, %1, %2, %0;" : "+l"(d) : "l"(a), "l"(b));
}
__device__ __forceinline__ ull mul2(ull a, ull b) {
    ull r; asm("mul.rn.f32x2 %0, %1, %2;" : "=l"(r) : "l"(a), "l"(b)); return r;
}
__device__ __forceinline__ ull dup2(float x) {
    ull r; asm("mov.b64 %0, {%1, %1};" : "=l"(r) : "f"(x)); return r;
}
__device__ __forceinline__ float2 up2(ull v) {
    float2 r; asm("mov.b64 {%0, %1}, %2;" : "=f"(r.x), "=f"(r.y) : "l"(v)); return r;
}

// ---------------------------------------------------------------------------
// Fused QKV projection. Block = 64 m-rows, computes Q,K,V tiles together.
// 128 threads; thread tile 8 rows x 4 cols x 3 matrices (FFMA2).
// X-row broadcast dup2s amortize across the 3 weight matrices: 0.83 B/FMA.
// ---------------------------------------------------------------------------
__global__ __launch_bounds__(128) void qkv_kernel(
    const float* __restrict__ x,
    const float* __restrict__ Wq,
    const float* __restrict__ Wk,
    const float* __restrict__ Wv)
{
    int mt  = blockIdx.x;           // 0..127
    int tid = threadIdx.x;
    int tx  = tid & 15;             // n col group (4 cols)
    int ty  = tid >> 4;             // m row group (8 rows)

    __shared__ float Xs[32][64];    // [c][m]
    __shared__ float Wqs[32][64];   // [c][n]
    __shared__ float Wks[32][64];
    __shared__ float Wvs[32][64];

    ull aq[8][2], ak[8][2], av[8][2];
#pragma unroll
    for (int i = 0; i < 8; ++i) {
        aq[i][0] = aq[i][1] = 0ULL;
        ak[i][0] = ak[i][1] = 0ULL;
        av[i][0] = av[i][1] = 0ULL;
    }

    int m_ld = tid >> 1;            // 0..63
    int cb   = (tid & 1) << 4;      // 0 or 16
    int c_wl = tid >> 2;            // 0..31
    int nb   = (tid & 3) << 4;      // 0,16,32,48

    for (int ct = 0; ct < CC; ct += 32) {
        // X tile transposed: each thread 16 c's of one m-row
        const float4* xr = (const float4*)(x + (size_t)(mt * 64 + m_ld) * CC + ct + cb);
#pragma unroll
        for (int i = 0; i < 4; ++i) {
            float4 u = xr[i];
            Xs[cb + 4 * i + 0][m_ld] = u.x;
            Xs[cb + 4 * i + 1][m_ld] = u.y;
            Xs[cb + 4 * i + 2][m_ld] = u.z;
            Xs[cb + 4 * i + 3][m_ld] = u.w;
        }
        // W tiles natural: each thread 4 float4 of one c-row per matrix
        const float4* wq = (const float4*)(Wq + (size_t)(ct + c_wl) * HH + nb);
        const float4* wk = (const float4*)(Wk + (size_t)(ct + c_wl) * HH + nb);
        const float4* wv = (const float4*)(Wv + (size_t)(ct + c_wl) * HH + nb);
#pragma unroll
        for (int i = 0; i < 4; ++i) {
            *(float4*)&Wqs[c_wl][nb + 4 * i] = wq[i];
            *(float4*)&Wks[c_wl][nb + 4 * i] = wk[i];
            *(float4*)&Wvs[c_wl][nb + 4 * i] = wv[i];
        }
        __syncthreads();

#pragma unroll 4
        for (int c = 0; c < 32; ++c) {
            float4 a0 = *(const float4*)&Xs[c][ty << 3];
            float4 a1 = *(const float4*)&Xs[c][(ty << 3) + 4];
            ulonglong2 bq = *(const ulonglong2*)&Wqs[c][tx << 2];
            ulonglong2 bk = *(const ulonglong2*)&Wks[c][tx << 2];
            ulonglong2 bv = *(const ulonglong2*)&Wvs[c][tx << 2];
            ull d[8];
            d[0] = dup2(a0.x); d[1] = dup2(a0.y); d[2] = dup2(a0.z); d[3] = dup2(a0.w);
            d[4] = dup2(a1.x); d[5] = dup2(a1.y); d[6] = dup2(a1.z); d[7] = dup2(a1.w);
#pragma unroll
            for (int i = 0; i < 8; ++i) {
                ffma2(aq[i][0], d[i], bq.x); ffma2(aq[i][1], d[i], bq.y);
                ffma2(ak[i][0], d[i], bk.x); ffma2(ak[i][1], d[i], bk.y);
                ffma2(av[i][0], d[i], bv.x); ffma2(av[i][1], d[i], bv.y);
            }
        }
        __syncthreads();
    }

#pragma unroll
    for (int i = 0; i < 8; ++i) {
        size_t row = (size_t)(mt * 64 + (ty << 3) + i) * HH + (tx << 2);
        float2 lo, hi;
        lo = up2(aq[i][0]); hi = up2(aq[i][1]);
        *(float4*)&g_q[row] = make_float4(lo.x, lo.y, hi.x, hi.y);
        lo = up2(ak[i][0]); hi = up2(ak[i][1]);
        *(float4*)&g_k[row] = make_float4(lo.x, lo.y, hi.x, hi.y);
        lo = up2(av[i][0]); hi = up2(av[i][1]);
        *(float4*)&g_v[row] = make_float4(lo.x, lo.y, hi.x, hi.y);
    }
}

// ---------------------------------------------------------------------------
// Flash-attention partial, kv-split. Block = 64 queries x 64-key tiles.
// 128 threads; S: 8q x 4k pair-packed FFMA2; PV: 8q x 4h FFMA2.
// Ps overlays Ks (dead after S) so static smem = exactly 48 KB.
// ---------------------------------------------------------------------------
__global__ __launch_bounds__(128) void attn_split_kernel()
{
    int blk = blockIdx.x;                 // 0..511
    int s   = blk & 3;
    int b   = (blk >> 2) & 3;
    int qt  = 31 - (blk >> 4);            // LPT: largest prefix first
    int tid = threadIdx.x;
    int tx  = tid & 15;
    int ty  = tid >> 4;

    int nkt = qt + 1;                     // 64-key tiles for this q-tile
    int t0  = (s * nkt) >> 2;
    int t1  = ((s + 1) * nkt) >> 2;

    float* po = g_po + ((size_t)(s * BB + b) * TT + qt * BQ) * HH;
    float* pm = g_pm + (size_t)(s * BB + b) * TT + qt * BQ;
    float* pl = g_pl + (size_t)(s * BB + b) * TT + qt * BQ;

    if (t0 == t1) {
        for (int i = tid; i < BQ * HH; i += 128) po[i] = 0.f;
        if (tid < BQ) { pm[tid] = -CUDART_INF_F; pl[tid] = 0.f; }
        return;
    }

    __shared__ float Qs[64][64];          // [h][q]
    __shared__ float KP[64][64];          // Ks [h][k], then Ps [q][k]
    __shared__ float Vs[64][64];          // [k][h]

    // load Q tile (transposed)
    {
        int q  = tid >> 1;
        int hb = (tid & 1) << 5;
        const float4* qr = (const float4*)(g_q + (size_t)(b * TT + qt * BQ + q) * HH + hb);
#pragma unroll
        for (int i = 0; i < 8; ++i) {
            float4 v = qr[i];
            Qs[hb + 4 * i + 0][q] = v.x;
            Qs[hb + 4 * i + 1][q] = v.y;
            Qs[hb + 4 * i + 2][q] = v.z;
            Qs[hb + 4 * i + 3][q] = v.w;
        }
    }

    ull o2[8][2];
    float m[8], l[8];
#pragma unroll
    for (int i = 0; i < 8; ++i) {
        m[i] = -CUDART_INF_F; l[i] = 0.f;
        o2[i][0] = o2[i][1] = 0ULL;
    }

    int k_ld  = tid >> 1;
    int hb_ld = (tid & 1) << 5;

    for (int kt = t0; kt < t1; ++kt) {
        __syncthreads();
        // K tile transposed into KP
        {
            const float4* kr = (const float4*)(g_k + (size_t)(b * TT + kt * BK + k_ld) * HH + hb_ld);
#pragma unroll
            for (int i = 0; i < 8; ++i) {
                float4 v = kr[i];
                KP[hb_ld + 4 * i + 0][k_ld] = v.x;
                KP[hb_ld + 4 * i + 1][k_ld] = v.y;
                KP[hb_ld + 4 * i + 2][k_ld] = v.z;
                KP[hb_ld + 4 * i + 3][k_ld] = v.w;
            }
            const float4* vsrc = (const float4*)(g_v + (size_t)(b * TT + kt * BK) * HH);
            float4* vdst = (float4*)&Vs[0][0];
#pragma unroll
            for (int r = 0; r < 8; ++r)
                vdst[tid + 128 * r] = vsrc[tid + 128 * r];
        }
        __syncthreads();

        // S = Q K^T : pair-packed rows (pairs from Qs loaded as ulonglong2)
        ull s2[4][4];
#pragma unroll
        for (int p = 0; p < 4; ++p)
#pragma unroll
            for (int j = 0; j < 4; ++j) s2[p][j] = 0ULL;

#pragma unroll 4
        for (int h = 0; h < HH; ++h) {
            ulonglong2 ap0 = *(const ulonglong2*)&Qs[h][ty << 3];       // pairs (0,1),(2,3)
            ulonglong2 ap1 = *(const ulonglong2*)&Qs[h][(ty << 3) + 4]; // pairs (4,5),(6,7)
            float4 bk4 = *(const float4*)&KP[h][tx << 2];
            ull b0 = dup2(bk4.x), b1 = dup2(bk4.y), b2 = dup2(bk4.z), b3 = dup2(bk4.w);
            ffma2(s2[0][0], ap0.x, b0); ffma2(s2[0][1], ap0.x, b1);
            ffma2(s2[0][2], ap0.x, b2); ffma2(s2[0][3], ap0.x, b3);
            ffma2(s2[1][0], ap0.y, b0); ffma2(s2[1][1], ap0.y, b1);
            ffma2(s2[1][2], ap0.y, b2); ffma2(s2[1][3], ap0.y, b3);
            ffma2(s2[2][0], ap1.x, b0); ffma2(s2[2][1], ap1.x, b1);
            ffma2(s2[2][2], ap1.x, b2); ffma2(s2[2][3], ap1.x, b3);
            ffma2(s2[3][0], ap1.y, b0); ffma2(s2[3][1], ap1.y, b1);
            ffma2(s2[3][2], ap1.y, b2); ffma2(s2[3][3], ap1.y, b3);
        }

        // unpack, scale, mask
        float sv[8][4];
#pragma unroll
        for (int p = 0; p < 4; ++p)
#pragma unroll
            for (int j = 0; j < 4; ++j) {
                float2 t = up2(s2[p][j]);
                sv[2 * p + 0][j] = t.x;
                sv[2 * p + 1][j] = t.y;
            }

        const float scale = 0.125f;
        bool diag = (kt == qt);
#pragma unroll
        for (int i = 0; i < 8; ++i) {
            int qg = qt * BQ + (ty << 3) + i;
#pragma unroll
            for (int j = 0; j < 4; ++j) {
                sv[i][j] *= scale;
                if (diag) {
                    int kg = kt * BK + (tx << 2) + j;
                    if (kg > qg) sv[i][j] = -CUDART_INF_F;
                }
            }
        }

        __syncthreads();   // all Ks reads done before Ps overwrites KP

        // online softmax per row, write P rows into KP
#pragma unroll
        for (int i = 0; i < 8; ++i) {
            float rm = fmaxf(fmaxf(sv[i][0], sv[i][1]), fmaxf(sv[i][2], sv[i][3]));
#pragma unroll
            for (int off = 8; off; off >>= 1)
                rm = fmaxf(rm, __shfl_xor_sync(0xffffffff, rm, off));
            float mn = fmaxf(m[i], rm);
            float corr = __expf(m[i] - mn);
            m[i] = mn;
            float rs = 0.f;
#pragma unroll
            for (int j = 0; j < 4; ++j) {
                float p = __expf(sv[i][j] - mn);
                sv[i][j] = p;
                rs += p;
            }
#pragma unroll
            for (int off = 8; off; off >>= 1)
                rs += __shfl_xor_sync(0xffffffff, rs, off);
            l[i] = l[i] * corr + rs;
            ull cd = dup2(corr);
            o2[i][0] = mul2(o2[i][0], cd);
            o2[i][1] = mul2(o2[i][1], cd);
            *(float4*)&KP[(ty << 3) + i][tx << 2] =
                make_float4(sv[i][0], sv[i][1], sv[i][2], sv[i][3]);
        }
        __syncthreads();

        // O += P V
#pragma unroll 2
        for (int k4 = 0; k4 < 16; ++k4) {
            float4 pr[8];
#pragma unroll
            for (int i = 0; i < 8; ++i)
                pr[i] = *(const float4*)&KP[(ty << 3) + i][k4 << 2];
#pragma unroll
            for (int r = 0; r < 4; ++r) {
                ulonglong2 vp = *(const ulonglong2*)&Vs[(k4 << 2) + r][tx << 2];
#pragma unroll
                for (int i = 0; i < 8; ++i) {
                    float pv = (r == 0) ? pr[i].x : (r == 1) ? pr[i].y
                             : (r == 2) ? pr[i].z : pr[i].w;
                    ull dp = dup2(pv);
                    ffma2(o2[i][0], dp, vp.x);
                    ffma2(o2[i][1], dp, vp.y);
                }
            }
        }
    }

    // write unnormalized partials
#pragma unroll
    for (int i = 0; i < 8; ++i) {
        int r_loc = (ty << 3) + i;
        float2 lo = up2(o2[i][0]);
        float2 hi = up2(o2[i][1]);
        *(float4*)&po[(size_t)r_loc * HH + (tx << 2)] =
            make_float4(lo.x, lo.y, hi.x, hi.y);
        if (tx == 0) { pm[r_loc] = m[i]; pl[r_loc] = l[i]; }
    }
}

// ---------------------------------------------------------------------------
// Combine kv-split partials.
// ---------------------------------------------------------------------------
__global__ __launch_bounds__(256) void combine_kernel(float* __restrict__ out)
{
    int idx = blockIdx.x * 256 + threadIdx.x;
    int row = idx >> 6;

    const int MS = BB * TT;
    const int PS = BB * TT * HH;

    float m0 = g_pm[row], m1 = g_pm[MS + row],
          m2 = g_pm[2 * MS + row], m3 = g_pm[3 * MS + row];
    float ms = fmaxf(fmaxf(m0, m1), fmaxf(m2, m3));
    float w0 = __expf(m0 - ms), w1 = __expf(m1 - ms);
    float w2 = __expf(m2 - ms), w3 = __expf(m3 - ms);
    float lt = w0 * g_pl[row] + w1 * g_pl[MS + row]
             + w2 * g_pl[2 * MS + row] + w3 * g_pl[3 * MS + row];
    float ov = w0 * g_po[idx] + w1 * g_po[PS + idx]
             + w2 * g_po[2 * PS + idx] + w3 * g_po[3 * PS + idx];
    out[idx] = ov / lt;
}

extern "C" void kernel_launch(void* const* d_in, const int* in_sizes, int n_in,
                              void* d_out, int out_size)
{
    const float* x  = (const float*)d_in[0];
    const float* Wq = (const float*)d_in[1];
    const float* Wk = (const float*)d_in[2];
    const float* Wv = (const float*)d_in[3];
    float* out = (float*)d_out;

    qkv_kernel<<<128, 128>>>(x, Wq, Wk, Wv);
    attn_split_kernel<<<32 * 4 * NS, 128>>>();
    combine_kernel<<<(BB * TT * HH) / 256, 256>>>(out);
}

// round 6
// speedup vs baseline: 1.1059x; 1.1059x over previous
#include <cuda_runtime.h>
#include <math_constants.h>

#define BB 4
#define TT 2048
#define CC 768
#define HH 64
#define BQ 32
#define BK 64
#define NS 4   // kv splits
#define CSPLIT 4

__device__ __align__(16) float g_q[BB * TT * HH];
__device__ __align__(16) float g_k[BB * TT * HH];
__device__ __align__(16) float g_v[BB * TT * HH];
// QKV c-split partials
__device__ __align__(16) float g_qp[CSPLIT * BB * TT * HH];
__device__ __align__(16) float g_kp[CSPLIT * BB * TT * HH];
__device__ __align__(16) float g_vp[CSPLIT * BB * TT * HH];
// attention kv-split partials
__device__ __align__(16) float g_po[NS * BB * TT * HH];
__device__ float g_pm[NS * BB * TT];
__device__ float g_pl[NS * BB * TT];

typedef unsigned long long ull;

__device__ __forceinline__ void ffma2(ull& d, ull a, ull b) {
    asm("fma.rn.f32x2 %0, %1, %2, %0;" : "+l"(d) : "l"(a), "l"(b));
}
__device__ __forceinline__ ull mul2(ull a, ull b) {
    ull r; asm("mul.rn.f32x2 %0, %1, %2;" : "=l"(r) : "l"(a), "l"(b)); return r;
}
__device__ __forceinline__ ull dup2(float x) {
    ull r; asm("mov.b64 %0, {%1, %1};" : "=l"(r) : "f"(x)); return r;
}
__device__ __forceinline__ float2 up2(ull v) {
    float2 r; asm("mov.b64 {%0, %1}, %2;" : "=f"(r.x), "=f"(r.y) : "l"(v)); return r;
}

// ---------------------------------------------------------------------------
// Fused QKV projection, C-split x4. Block = 64 m-rows x (Q,K,V) over a
// 192-wide slice of C. grid = 512. Thread tile 8 rows x 4 cols x 3 matrices.
// ---------------------------------------------------------------------------
__global__ __launch_bounds__(128) void qkv_partial_kernel(
    const float* __restrict__ x,
    const float* __restrict__ Wq,
    const float* __restrict__ Wk,
    const float* __restrict__ Wv)
{
    int blk = blockIdx.x;
    int mt  = blk >> 2;             // 0..127
    int cs  = blk & 3;              // c-split index
    int ct0 = cs * (CC / CSPLIT);   // 192-wide slice

    int tid = threadIdx.x;
    int tx  = tid & 15;
    int ty  = tid >> 4;

    __shared__ float Xs[32][64];
    __shared__ float Wqs[32][64];
    __shared__ float Wks[32][64];
    __shared__ float Wvs[32][64];

    ull aq[8][2], ak[8][2], av[8][2];
#pragma unroll
    for (int i = 0; i < 8; ++i) {
        aq[i][0] = aq[i][1] = 0ULL;
        ak[i][0] = ak[i][1] = 0ULL;
        av[i][0] = av[i][1] = 0ULL;
    }

    int m_ld = tid >> 1;
    int cb   = (tid & 1) << 4;
    int c_wl = tid >> 2;
    int nb   = (tid & 3) << 4;

    for (int ct = ct0; ct < ct0 + CC / CSPLIT; ct += 32) {
        const float4* xr = (const float4*)(x + (size_t)(mt * 64 + m_ld) * CC + ct + cb);
#pragma unroll
        for (int i = 0; i < 4; ++i) {
            float4 u = xr[i];
            Xs[cb + 4 * i + 0][m_ld] = u.x;
            Xs[cb + 4 * i + 1][m_ld] = u.y;
            Xs[cb + 4 * i + 2][m_ld] = u.z;
            Xs[cb + 4 * i + 3][m_ld] = u.w;
        }
        const float4* wq = (const float4*)(Wq + (size_t)(ct + c_wl) * HH + nb);
        const float4* wk = (const float4*)(Wk + (size_t)(ct + c_wl) * HH + nb);
        const float4* wv = (const float4*)(Wv + (size_t)(ct + c_wl) * HH + nb);
#pragma unroll
        for (int i = 0; i < 4; ++i) {
            *(float4*)&Wqs[c_wl][nb + 4 * i] = wq[i];
            *(float4*)&Wks[c_wl][nb + 4 * i] = wk[i];
            *(float4*)&Wvs[c_wl][nb + 4 * i] = wv[i];
        }
        __syncthreads();

#pragma unroll 4
        for (int c = 0; c < 32; ++c) {
            float4 a0 = *(const float4*)&Xs[c][ty << 3];
            float4 a1 = *(const float4*)&Xs[c][(ty << 3) + 4];
            ulonglong2 bq = *(const ulonglong2*)&Wqs[c][tx << 2];
            ulonglong2 bk = *(const ulonglong2*)&Wks[c][tx << 2];
            ulonglong2 bv = *(const ulonglong2*)&Wvs[c][tx << 2];
            ull d[8];
            d[0] = dup2(a0.x); d[1] = dup2(a0.y); d[2] = dup2(a0.z); d[3] = dup2(a0.w);
            d[4] = dup2(a1.x); d[5] = dup2(a1.y); d[6] = dup2(a1.z); d[7] = dup2(a1.w);
#pragma unroll
            for (int i = 0; i < 8; ++i) {
                ffma2(aq[i][0], d[i], bq.x); ffma2(aq[i][1], d[i], bq.y);
                ffma2(ak[i][0], d[i], bk.x); ffma2(ak[i][1], d[i], bk.y);
                ffma2(av[i][0], d[i], bv.x); ffma2(av[i][1], d[i], bv.y);
            }
        }
        __syncthreads();
    }

    size_t pbase = (size_t)cs * (BB * TT * HH);
#pragma unroll
    for (int i = 0; i < 8; ++i) {
        size_t row = pbase + (size_t)(mt * 64 + (ty << 3) + i) * HH + (tx << 2);
        float2 lo, hi;
        lo = up2(aq[i][0]); hi = up2(aq[i][1]);
        *(float4*)&g_qp[row] = make_float4(lo.x, lo.y, hi.x, hi.y);
        lo = up2(ak[i][0]); hi = up2(ak[i][1]);
        *(float4*)&g_kp[row] = make_float4(lo.x, lo.y, hi.x, hi.y);
        lo = up2(av[i][0]); hi = up2(av[i][1]);
        *(float4*)&g_vp[row] = make_float4(lo.x, lo.y, hi.x, hi.y);
    }
}

// ---------------------------------------------------------------------------
// Sum the 4 C-split partials into g_q/g_k/g_v. float4-wide.
// ---------------------------------------------------------------------------
__global__ __launch_bounds__(256) void qkv_add_kernel()
{
    int i4 = blockIdx.x * 256 + threadIdx.x;      // float4 index
    const int P4 = (BB * TT * HH) / 4;            // 131072

    const float4* qp = (const float4*)g_qp;
    const float4* kp = (const float4*)g_kp;
    const float4* vp = (const float4*)g_vp;

    float4 q0 = qp[i4], q1 = qp[P4 + i4], q2 = qp[2 * P4 + i4], q3 = qp[3 * P4 + i4];
    ((float4*)g_q)[i4] = make_float4(q0.x + q1.x + q2.x + q3.x,
                                     q0.y + q1.y + q2.y + q3.y,
                                     q0.z + q1.z + q2.z + q3.z,
                                     q0.w + q1.w + q2.w + q3.w);
    float4 k0 = kp[i4], k1 = kp[P4 + i4], k2 = kp[2 * P4 + i4], k3 = kp[3 * P4 + i4];
    ((float4*)g_k)[i4] = make_float4(k0.x + k1.x + k2.x + k3.x,
                                     k0.y + k1.y + k2.y + k3.y,
                                     k0.z + k1.z + k2.z + k3.z,
                                     k0.w + k1.w + k2.w + k3.w);
    float4 v0 = vp[i4], v1 = vp[P4 + i4], v2 = vp[2 * P4 + i4], v3 = vp[3 * P4 + i4];
    ((float4*)g_v)[i4] = make_float4(v0.x + v1.x + v2.x + v3.x,
                                     v0.y + v1.y + v2.y + v3.y,
                                     v0.z + v1.z + v2.z + v3.z,
                                     v0.w + v1.w + v2.w + v3.w);
}

// ---------------------------------------------------------------------------
// Flash-attention partial, kv-split (R4-proven version). Block = 32 queries.
// 128 threads; 4x4 register tiles, FFMA2 GEMM microkernels.
// ---------------------------------------------------------------------------
__global__ __launch_bounds__(128) void attn_split_kernel()
{
    int blk = blockIdx.x;                 // 0..1023, LPT order
    int s   = blk & 3;
    int b   = (blk >> 2) & 3;
    int qt  = 63 - (blk >> 4);
    int tid = threadIdx.x;
    int tx  = tid & 15;
    int ty  = tid >> 4;

    int nkt = (qt + 2) >> 1;
    int t0  = (s * nkt) >> 2;
    int t1  = ((s + 1) * nkt) >> 2;

    float* po = g_po + ((size_t)(s * BB + b) * TT + qt * BQ) * HH;
    float* pm = g_pm + (size_t)(s * BB + b) * TT + qt * BQ;
    float* pl = g_pl + (size_t)(s * BB + b) * TT + qt * BQ;

    if (t0 == t1) {
        for (int i = tid; i < BQ * HH; i += 128) po[i] = 0.f;
        if (tid < BQ) { pm[tid] = -CUDART_INF_F; pl[tid] = 0.f; }
        return;
    }

    __shared__ float Qs[64][32];
    __shared__ float Ks[64][64];
    __shared__ float Vs[64][64];
    __shared__ float Ps[32][64];

    {
        int q  = tid >> 2;
        int hb = (tid & 3) << 4;
        const float4* qr = (const float4*)(g_q + (size_t)(b * TT + qt * BQ + q) * HH + hb);
#pragma unroll
        for (int i = 0; i < 4; ++i) {
            float4 v = qr[i];
            Qs[hb + 4 * i + 0][q] = v.x;
            Qs[hb + 4 * i + 1][q] = v.y;
            Qs[hb + 4 * i + 2][q] = v.z;
            Qs[hb + 4 * i + 3][q] = v.w;
        }
    }

    ull o2[4][2];
    float m[4], l[4];
#pragma unroll
    for (int i = 0; i < 4; ++i) {
        m[i] = -CUDART_INF_F; l[i] = 0.f;
        o2[i][0] = 0ULL; o2[i][1] = 0ULL;
    }

    int k_ld  = tid >> 2;
    int hb_ld = (tid & 3) << 4;

    for (int kt = t0; kt < t1; ++kt) {
        __syncthreads();
        {
#pragma unroll
            for (int kk = 0; kk < 2; ++kk) {
                int kx = k_ld + kk * 32;
                const float4* kr = (const float4*)(g_k + (size_t)(b * TT + kt * BK + kx) * HH + hb_ld);
#pragma unroll
                for (int i = 0; i < 4; ++i) {
                    float4 v = kr[i];
                    Ks[hb_ld + 4 * i + 0][kx] = v.x;
                    Ks[hb_ld + 4 * i + 1][kx] = v.y;
                    Ks[hb_ld + 4 * i + 2][kx] = v.z;
                    Ks[hb_ld + 4 * i + 3][kx] = v.w;
                }
            }
            const float4* vsrc = (const float4*)(g_v + (size_t)(b * TT + kt * BK) * HH);
            float4* vdst = (float4*)&Vs[0][0];
#pragma unroll
            for (int r = 0; r < 8; ++r)
                vdst[tid + 128 * r] = vsrc[tid + 128 * r];
        }
        __syncthreads();

        ull s2[4][2];
#pragma unroll
        for (int i = 0; i < 4; ++i) { s2[i][0] = 0ULL; s2[i][1] = 0ULL; }

#pragma unroll 8
        for (int h = 0; h < HH; ++h) {
            float4 a = *(const float4*)&Qs[h][ty << 2];
            ulonglong2 bp = *(const ulonglong2*)&Ks[h][tx << 2];
            ull a0 = dup2(a.x), a1 = dup2(a.y), a2 = dup2(a.z), a3 = dup2(a.w);
            ffma2(s2[0][0], a0, bp.x); ffma2(s2[0][1], a0, bp.y);
            ffma2(s2[1][0], a1, bp.x); ffma2(s2[1][1], a1, bp.y);
            ffma2(s2[2][0], a2, bp.x); ffma2(s2[2][1], a2, bp.y);
            ffma2(s2[3][0], a3, bp.x); ffma2(s2[3][1], a3, bp.y);
        }

        float sv[4][4];
#pragma unroll
        for (int i = 0; i < 4; ++i) {
            float2 lo = up2(s2[i][0]);
            float2 hi = up2(s2[i][1]);
            sv[i][0] = lo.x; sv[i][1] = lo.y; sv[i][2] = hi.x; sv[i][3] = hi.y;
        }

        const float scale = 0.125f;
        bool lastkt = (kt == nkt - 1);
#pragma unroll
        for (int i = 0; i < 4; ++i) {
            int qg = qt * BQ + (ty << 2) + i;
#pragma unroll
            for (int j = 0; j < 4; ++j) {
                sv[i][j] *= scale;
                if (lastkt) {
                    int kg = kt * BK + (tx << 2) + j;
                    if (kg > qg) sv[i][j] = -CUDART_INF_F;
                }
            }
        }

#pragma unroll
        for (int i = 0; i < 4; ++i) {
            float rm = fmaxf(fmaxf(sv[i][0], sv[i][1]), fmaxf(sv[i][2], sv[i][3]));
#pragma unroll
            for (int off = 8; off; off >>= 1)
                rm = fmaxf(rm, __shfl_xor_sync(0xffffffff, rm, off));
            float mn = fmaxf(m[i], rm);
            float corr = __expf(m[i] - mn);
            m[i] = mn;
            float rs = 0.f;
#pragma unroll
            for (int j = 0; j < 4; ++j) {
                float p = __expf(sv[i][j] - mn);
                sv[i][j] = p;
                rs += p;
            }
#pragma unroll
            for (int off = 8; off; off >>= 1)
                rs += __shfl_xor_sync(0xffffffff, rs, off);
            l[i] = l[i] * corr + rs;
            ull cd = dup2(corr);
            o2[i][0] = mul2(o2[i][0], cd);
            o2[i][1] = mul2(o2[i][1], cd);
            *(float4*)&Ps[(ty << 2) + i][tx << 2] =
                make_float4(sv[i][0], sv[i][1], sv[i][2], sv[i][3]);
        }
        __syncthreads();

#pragma unroll 4
        for (int k4 = 0; k4 < 16; ++k4) {
            float4 p0 = *(const float4*)&Ps[(ty << 2) + 0][k4 << 2];
            float4 p1 = *(const float4*)&Ps[(ty << 2) + 1][k4 << 2];
            float4 p2 = *(const float4*)&Ps[(ty << 2) + 2][k4 << 2];
            float4 p3 = *(const float4*)&Ps[(ty << 2) + 3][k4 << 2];
#pragma unroll
            for (int r = 0; r < 4; ++r) {
                ulonglong2 vp = *(const ulonglong2*)&Vs[(k4 << 2) + r][tx << 2];
                float pa = (r == 0) ? p0.x : (r == 1) ? p0.y : (r == 2) ? p0.z : p0.w;
                float pb = (r == 0) ? p1.x : (r == 1) ? p1.y : (r == 2) ? p1.z : p1.w;
                float pc = (r == 0) ? p2.x : (r == 1) ? p2.y : (r == 2) ? p2.z : p2.w;
                float pd = (r == 0) ? p3.x : (r == 1) ? p3.y : (r == 2) ? p3.z : p3.w;
                ull da = dup2(pa), db = dup2(pb), dc = dup2(pc), dd = dup2(pd);
                ffma2(o2[0][0], da, vp.x); ffma2(o2[0][1], da, vp.y);
                ffma2(o2[1][0], db, vp.x); ffma2(o2[1][1], db, vp.y);
                ffma2(o2[2][0], dc, vp.x); ffma2(o2[2][1], dc, vp.y);
                ffma2(o2[3][0], dd, vp.x); ffma2(o2[3][1], dd, vp.y);
            }
        }
    }

#pragma unroll
    for (int i = 0; i < 4; ++i) {
        int r_loc = (ty << 2) + i;
        float2 lo = up2(o2[i][0]);
        float2 hi = up2(o2[i][1]);
        *(float4*)&po[(size_t)r_loc * HH + (tx << 2)] =
            make_float4(lo.x, lo.y, hi.x, hi.y);
        if (tx == 0) { pm[r_loc] = m[i]; pl[r_loc] = l[i]; }
    }
}

// ---------------------------------------------------------------------------
// Combine kv-split partials.
// ---------------------------------------------------------------------------
__global__ __launch_bounds__(256) void combine_kernel(float* __restrict__ out)
{
    int idx = blockIdx.x * 256 + threadIdx.x;
    int row = idx >> 6;

    const int MS = BB * TT;
    const int PS = BB * TT * HH;

    float m0 = g_pm[row], m1 = g_pm[MS + row],
          m2 = g_pm[2 * MS + row], m3 = g_pm[3 * MS + row];
    float ms = fmaxf(fmaxf(m0, m1), fmaxf(m2, m3));
    float w0 = __expf(m0 - ms), w1 = __expf(m1 - ms);
    float w2 = __expf(m2 - ms), w3 = __expf(m3 - ms);
    float lt = w0 * g_pl[row] + w1 * g_pl[MS + row]
             + w2 * g_pl[2 * MS + row] + w3 * g_pl[3 * MS + row];
    float ov = w0 * g_po[idx] + w1 * g_po[PS + idx]
             + w2 * g_po[2 * PS + idx] + w3 * g_po[3 * PS + idx];
    out[idx] = ov / lt;
}

extern "C" void kernel_launch(void* const* d_in, const int* in_sizes, int n_in,
                              void* d_out, int out_size)
{
    const float* x  = (const float*)d_in[0];
    const float* Wq = (const float*)d_in[1];
    const float* Wk = (const float*)d_in[2];
    const float* Wv = (const float*)d_in[3];
    float* out = (float*)d_out;

    qkv_partial_kernel<<<128 * CSPLIT, 128>>>(x, Wq, Wk, Wv);
    qkv_add_kernel<<<(BB * TT * HH) / 4 / 256, 256>>>();
    attn_split_kernel<<<64 * 4 * NS, 128>>>();
    combine_kernel<<<(BB * TT * HH) / 256, 256>>>(out);
}

// round 8
// speedup vs baseline: 1.4901x; 1.3475x over previous
#include <cuda_runtime.h>
#include <math_constants.h>
#include <cstdint>

#define BB 4
#define TT 2048
#define CC 768
#define HH 64
#define BQ 32
#define BK 64
#define NS 4   // kv splits

__device__ __align__(16) float g_q[BB * TT * HH];
__device__ __align__(16) float g_k[BB * TT * HH];
__device__ __align__(16) float g_v[BB * TT * HH];
__device__ __align__(16) uint32_t g_wt[3 * HH * CC];   // fused W^T, tf32 bits
__device__ __align__(16) float g_po[NS * BB * TT * HH];
__device__ float g_pm[NS * BB * TT];
__device__ float g_pl[NS * BB * TT];

typedef unsigned long long ull;

__device__ __forceinline__ void ffma2(ull& d, ull a, ull b) {
    asm("fma.rn.f32x2 %0, %1, %2, %0;" : "+l"(d) : "l"(a), "l"(b));
}
__device__ __forceinline__ ull mul2(ull a, ull b) {
    ull r; asm("mul.rn.f32x2 %0, %1, %2;" : "=l"(r) : "l"(a), "l"(b)); return r;
}
__device__ __forceinline__ ull dup2(float x) {
    ull r; asm("mov.b64 %0, {%1, %1};" : "=l"(r) : "f"(x)); return r;
}
__device__ __forceinline__ float2 up2(ull v) {
    float2 r; asm("mov.b64 {%0, %1}, %2;" : "=f"(r.x), "=f"(r.y) : "l"(v)); return r;
}
__device__ __forceinline__ uint32_t tf32r(float f) {
    uint32_t u; asm("cvt.rna.tf32.f32 %0, %1;" : "=r"(u) : "f"(f)); return u;
}
__device__ __forceinline__ void mma_tf32(float* c, const uint32_t* a, const uint32_t* b) {
    asm volatile(
        "mma.sync.aligned.m16n8k8.row.col.f32.tf32.tf32.f32 "
        "{%0,%1,%2,%3}, {%4,%5,%6,%7}, {%8,%9}, {%0,%1,%2,%3};"
        : "+f"(c[0]), "+f"(c[1]), "+f"(c[2]), "+f"(c[3])
        : "r"(a[0]), "r"(a[1]), "r"(a[2]), "r"(a[3]), "r"(b[0]), "r"(b[1]));
}

// ---------------------------------------------------------------------------
// Prep: fused transposed weights Wt[n=192][k=768], tf32-rounded.
// n in [0,64)=Q, [64,128)=K, [128,192)=V.
// ---------------------------------------------------------------------------
__global__ __launch_bounds__(256) void wt_kernel(
    const float* __restrict__ Wq,
    const float* __restrict__ Wk,
    const float* __restrict__ Wv)
{
    int i = blockIdx.x * 256 + threadIdx.x;     // < 192*768
    int n = i / CC;
    int k = i - n * CC;
    const float* W = (n < 64) ? Wq : (n < 128) ? Wk : Wv;
    g_wt[i] = tf32r(W[k * HH + (n & 63)]);
}

// ---------------------------------------------------------------------------
// QKV on tensor cores via mma.sync tf32. Block = 32 rows x 192 cols (Q|K|V).
// 256 threads = 8 warps in 2(m) x 4(n); warp tile m16 x n48 (6 n8 tiles).
// K staged 32-wide in smem (pitch 36: conflict-free fragment gathers).
// ---------------------------------------------------------------------------
__global__ __launch_bounds__(256) void qkv_mma_kernel(const float* __restrict__ x)
{
    __shared__ uint32_t As[32][36];
    __shared__ uint32_t Bs[192][36];

    int tid = threadIdx.x;
    int wid = tid >> 5, lane = tid & 31;
    int g   = lane >> 2, tig = lane & 3;
    int mw  = wid >> 2, nw = wid & 3;     // 2 x 4 warp grid
    int mt  = blockIdx.x;                 // 0..255 (32 rows each)

    float acc[6][4];
#pragma unroll
    for (int t = 0; t < 6; ++t)
#pragma unroll
        for (int j = 0; j < 4; ++j) acc[t][j] = 0.f;

    int ar = tid >> 3;                    // A load: row 0..31
    int ak = (tid & 7) << 2;              // k quad

    for (int ck = 0; ck < CC; ck += 32) {
        // stage A (x rows, tf32-rounded)
        {
            const float4* xr = (const float4*)(x + (size_t)(mt * 32 + ar) * CC + ck + ak);
            float4 v = *xr;
            uint4 t = make_uint4(tf32r(v.x), tf32r(v.y), tf32r(v.z), tf32r(v.w));
            *(uint4*)&As[ar][ak] = t;
        }
        // stage B (Wt rows, already tf32)
#pragma unroll
        for (int j = 0; j < 6; ++j) {
            int idx = tid + j * 256;      // 0..1535
            int n  = idx >> 3;
            int kq = (idx & 7) << 2;
            uint4 t = *(const uint4*)&g_wt[(size_t)n * CC + ck + kq];
            *(uint4*)&Bs[n][kq] = t;
        }
        __syncthreads();

#pragma unroll
        for (int ks = 0; ks < 4; ++ks) {
            int k0 = ks << 3;
            uint32_t a[4];
            int r0 = (mw << 4) + g;
            a[0] = As[r0][k0 + tig];
            a[1] = As[r0 + 8][k0 + tig];
            a[2] = As[r0][k0 + tig + 4];
            a[3] = As[r0 + 8][k0 + tig + 4];
#pragma unroll
            for (int t = 0; t < 6; ++t) {
                int n0 = nw * 48 + t * 8;
                uint32_t b[2];
                b[0] = Bs[n0 + g][k0 + tig];
                b[1] = Bs[n0 + g][k0 + tig + 4];
                mma_tf32(acc[t], a, b);
            }
        }
        __syncthreads();
    }

    // epilogue: c0,c1 = (row g, cols 2tig,2tig+1); c2,c3 = row g+8
    int row0 = mt * 32 + (mw << 4) + g;
#pragma unroll
    for (int t = 0; t < 6; ++t) {
        int n0  = nw * 48 + t * 8;
        float* G = (n0 < 64) ? g_q : (n0 < 128) ? g_k : g_v;
        int ncol = (n0 & 63) + (tig << 1);
        *(float2*)&G[(size_t)row0 * HH + ncol] = make_float2(acc[t][0], acc[t][1]);
        *(float2*)&G[(size_t)(row0 + 8) * HH + ncol] = make_float2(acc[t][2], acc[t][3]);
    }
}

// ---------------------------------------------------------------------------
// Flash-attention partial, kv-split (proven R4 version, unchanged).
// ---------------------------------------------------------------------------
__global__ __launch_bounds__(128) void attn_split_kernel()
{
    int blk = blockIdx.x;
    int s   = blk & 3;
    int b   = (blk >> 2) & 3;
    int qt  = 63 - (blk >> 4);
    int tid = threadIdx.x;
    int tx  = tid & 15;
    int ty  = tid >> 4;

    int nkt = (qt + 2) >> 1;
    int t0  = (s * nkt) >> 2;
    int t1  = ((s + 1) * nkt) >> 2;

    float* po = g_po + ((size_t)(s * BB + b) * TT + qt * BQ) * HH;
    float* pm = g_pm + (size_t)(s * BB + b) * TT + qt * BQ;
    float* pl = g_pl + (size_t)(s * BB + b) * TT + qt * BQ;

    if (t0 == t1) {
        for (int i = tid; i < BQ * HH; i += 128) po[i] = 0.f;
        if (tid < BQ) { pm[tid] = -CUDART_INF_F; pl[tid] = 0.f; }
        return;
    }

    __shared__ float Qs[64][32];
    __shared__ float Ks[64][64];
    __shared__ float Vs[64][64];
    __shared__ float Ps[32][64];

    {
        int q  = tid >> 2;
        int hb = (tid & 3) << 4;
        const float4* qr = (const float4*)(g_q + (size_t)(b * TT + qt * BQ + q) * HH + hb);
#pragma unroll
        for (int i = 0; i < 4; ++i) {
            float4 v = qr[i];
            Qs[hb + 4 * i + 0][q] = v.x;
            Qs[hb + 4 * i + 1][q] = v.y;
            Qs[hb + 4 * i + 2][q] = v.z;
            Qs[hb + 4 * i + 3][q] = v.w;
        }
    }

    ull o2[4][2];
    float m[4], l[4];
#pragma unroll
    for (int i = 0; i < 4; ++i) {
        m[i] = -CUDART_INF_F; l[i] = 0.f;
        o2[i][0] = 0ULL; o2[i][1] = 0ULL;
    }

    int k_ld  = tid >> 2;
    int hb_ld = (tid & 3) << 4;

    for (int kt = t0; kt < t1; ++kt) {
        __syncthreads();
        {
#pragma unroll
            for (int kk = 0; kk < 2; ++kk) {
                int kx = k_ld + kk * 32;
                const float4* kr = (const float4*)(g_k + (size_t)(b * TT + kt * BK + kx) * HH + hb_ld);
#pragma unroll
                for (int i = 0; i < 4; ++i) {
                    float4 v = kr[i];
                    Ks[hb_ld + 4 * i + 0][kx] = v.x;
                    Ks[hb_ld + 4 * i + 1][kx] = v.y;
                    Ks[hb_ld + 4 * i + 2][kx] = v.z;
                    Ks[hb_ld + 4 * i + 3][kx] = v.w;
                }
            }
            const float4* vsrc = (const float4*)(g_v + (size_t)(b * TT + kt * BK) * HH);
            float4* vdst = (float4*)&Vs[0][0];
#pragma unroll
            for (int r = 0; r < 8; ++r)
                vdst[tid + 128 * r] = vsrc[tid + 128 * r];
        }
        __syncthreads();

        ull s2[4][2];
#pragma unroll
        for (int i = 0; i < 4; ++i) { s2[i][0] = 0ULL; s2[i][1] = 0ULL; }

#pragma unroll 8
        for (int h = 0; h < HH; ++h) {
            float4 a = *(const float4*)&Qs[h][ty << 2];
            ulonglong2 bp = *(const ulonglong2*)&Ks[h][tx << 2];
            ull a0 = dup2(a.x), a1 = dup2(a.y), a2 = dup2(a.z), a3 = dup2(a.w);
            ffma2(s2[0][0], a0, bp.x); ffma2(s2[0][1], a0, bp.y);
            ffma2(s2[1][0], a1, bp.x); ffma2(s2[1][1], a1, bp.y);
            ffma2(s2[2][0], a2, bp.x); ffma2(s2[2][1], a2, bp.y);
            ffma2(s2[3][0], a3, bp.x); ffma2(s2[3][1], a3, bp.y);
        }

        float sv[4][4];
#pragma unroll
        for (int i = 0; i < 4; ++i) {
            float2 lo = up2(s2[i][0]);
            float2 hi = up2(s2[i][1]);
            sv[i][0] = lo.x; sv[i][1] = lo.y; sv[i][2] = hi.x; sv[i][3] = hi.y;
        }

        const float scale = 0.125f;
        bool lastkt = (kt == nkt - 1);
#pragma unroll
        for (int i = 0; i < 4; ++i) {
            int qg = qt * BQ + (ty << 2) + i;
#pragma unroll
            for (int j = 0; j < 4; ++j) {
                sv[i][j] *= scale;
                if (lastkt) {
                    int kg = kt * BK + (tx << 2) + j;
                    if (kg > qg) sv[i][j] = -CUDART_INF_F;
                }
            }
        }

#pragma unroll
        for (int i = 0; i < 4; ++i) {
            float rm = fmaxf(fmaxf(sv[i][0], sv[i][1]), fmaxf(sv[i][2], sv[i][3]));
#pragma unroll
            for (int off = 8; off; off >>= 1)
                rm = fmaxf(rm, __shfl_xor_sync(0xffffffff, rm, off));
            float mn = fmaxf(m[i], rm);
            float corr = __expf(m[i] - mn);
            m[i] = mn;
            float rs = 0.f;
#pragma unroll
            for (int j = 0; j < 4; ++j) {
                float p = __expf(sv[i][j] - mn);
                sv[i][j] = p;
                rs += p;
            }
#pragma unroll
            for (int off = 8; off; off >>= 1)
                rs += __shfl_xor_sync(0xffffffff, rs, off);
            l[i] = l[i] * corr + rs;
            ull cd = dup2(corr);
            o2[i][0] = mul2(o2[i][0], cd);
            o2[i][1] = mul2(o2[i][1], cd);
            *(float4*)&Ps[(ty << 2) + i][tx << 2] =
                make_float4(sv[i][0], sv[i][1], sv[i][2], sv[i][3]);
        }
        __syncthreads();

#pragma unroll 4
        for (int k4 = 0; k4 < 16; ++k4) {
            float4 p0 = *(const float4*)&Ps[(ty << 2) + 0][k4 << 2];
            float4 p1 = *(const float4*)&Ps[(ty << 2) + 1][k4 << 2];
            float4 p2 = *(const float4*)&Ps[(ty << 2) + 2][k4 << 2];
            float4 p3 = *(const float4*)&Ps[(ty << 2) + 3][k4 << 2];
#pragma unroll
            for (int r = 0; r < 4; ++r) {
                ulonglong2 vp = *(const ulonglong2*)&Vs[(k4 << 2) + r][tx << 2];
                float pa = (r == 0) ? p0.x : (r == 1) ? p0.y : (r == 2) ? p0.z : p0.w;
                float pb = (r == 0) ? p1.x : (r == 1) ? p1.y : (r == 2) ? p1.z : p1.w;
                float pc = (r == 0) ? p2.x : (r == 1) ? p2.y : (r == 2) ? p2.z : p2.w;
                float pd = (r == 0) ? p3.x : (r == 1) ? p3.y : (r == 2) ? p3.z : p3.w;
                ull da = dup2(pa), db = dup2(pb), dc = dup2(pc), dd = dup2(pd);
                ffma2(o2[0][0], da, vp.x); ffma2(o2[0][1], da, vp.y);
                ffma2(o2[1][0], db, vp.x); ffma2(o2[1][1], db, vp.y);
                ffma2(o2[2][0], dc, vp.x); ffma2(o2[2][1], dc, vp.y);
                ffma2(o2[3][0], dd, vp.x); ffma2(o2[3][1], dd, vp.y);
            }
        }
    }

#pragma unroll
    for (int i = 0; i < 4; ++i) {
        int r_loc = (ty << 2) + i;
        float2 lo = up2(o2[i][0]);
        float2 hi = up2(o2[i][1]);
        *(float4*)&po[(size_t)r_loc * HH + (tx << 2)] =
            make_float4(lo.x, lo.y, hi.x, hi.y);
        if (tx == 0) { pm[r_loc] = m[i]; pl[r_loc] = l[i]; }
    }
}

// ---------------------------------------------------------------------------
// Combine kv-split partials.
// ---------------------------------------------------------------------------
__global__ __launch_bounds__(256) void combine_kernel(float* __restrict__ out)
{
    int idx = blockIdx.x * 256 + threadIdx.x;
    int row = idx >> 6;

    const int MS = BB * TT;
    const int PS = BB * TT * HH;

    float m0 = g_pm[row], m1 = g_pm[MS + row],
          m2 = g_pm[2 * MS + row], m3 = g_pm[3 * MS + row];
    float ms = fmaxf(fmaxf(m0, m1), fmaxf(m2, m3));
    float w0 = __expf(m0 - ms), w1 = __expf(m1 - ms);
    float w2 = __expf(m2 - ms), w3 = __expf(m3 - ms);
    float lt = w0 * g_pl[row] + w1 * g_pl[MS + row]
             + w2 * g_pl[2 * MS + row] + w3 * g_pl[3 * MS + row];
    float ov = w0 * g_po[idx] + w1 * g_po[PS + idx]
             + w2 * g_po[2 * PS + idx] + w3 * g_po[3 * PS + idx];
    out[idx] = ov / lt;
}

extern "C" void kernel_launch(void* const* d_in, const int* in_sizes, int n_in,
                              void* d_out, int out_size)
{
    const float* x  = (const float*)d_in[0];
    const float* Wq = (const float*)d_in[1];
    const float* Wk = (const float*)d_in[2];
    const float* Wv = (const float*)d_in[3];
    float* out = (float*)d_out;

    wt_kernel<<<(3 * HH * CC) / 256, 256>>>(Wq, Wk, Wv);
    qkv_mma_kernel<<<(BB * TT) / 32, 256>>>(x);
    attn_split_kernel<<<64 * 4 * NS, 128>>>();
    combine_kernel<<<(BB * TT * HH) / 256, 256>>>(out);
}

// round 9
// speedup vs baseline: 2.2981x; 1.5422x over previous
#include <cuda_runtime.h>
#include <math_constants.h>
#include <cuda_fp16.h>
#include <cstdint>

#define BB 4
#define TT 2048
#define CC 768
#define HH 64
#define NS 4   // kv splits
#define BQM 128
#define BKN 64

__device__ __align__(16) float g_q[BB * TT * HH];
__device__ __align__(16) float g_k[BB * TT * HH];
__device__ __align__(16) float g_v[BB * TT * HH];
__device__ __align__(16) uint32_t g_wt[3 * HH * CC];   // fused W^T, tf32 bits
__device__ __align__(16) float g_po[NS * BB * TT * HH];
__device__ float g_pm[NS * BB * TT];
__device__ float g_pl[NS * BB * TT];

__device__ __forceinline__ uint32_t tf32r(float f) {
    uint32_t u; asm("cvt.rna.tf32.f32 %0, %1;" : "=r"(u) : "f"(f)); return u;
}
__device__ __forceinline__ void mma_tf32(float* c, const uint32_t* a, const uint32_t* b) {
    asm volatile(
        "mma.sync.aligned.m16n8k8.row.col.f32.tf32.tf32.f32 "
        "{%0,%1,%2,%3}, {%4,%5,%6,%7}, {%8,%9}, {%0,%1,%2,%3};"
        : "+f"(c[0]), "+f"(c[1]), "+f"(c[2]), "+f"(c[3])
        : "r"(a[0]), "r"(a[1]), "r"(a[2]), "r"(a[3]), "r"(b[0]), "r"(b[1]));
}
__device__ __forceinline__ void mma_f16(float* c, const uint32_t* a, uint32_t b0, uint32_t b1) {
    asm volatile(
        "mma.sync.aligned.m16n8k16.row.col.f32.f16.f16.f32 "
        "{%0,%1,%2,%3}, {%4,%5,%6,%7}, {%8,%9}, {%0,%1,%2,%3};"
        : "+f"(c[0]), "+f"(c[1]), "+f"(c[2]), "+f"(c[3])
        : "r"(a[0]), "r"(a[1]), "r"(a[2]), "r"(a[3]), "r"(b0), "r"(b1));
}
__device__ __forceinline__ uint32_t packh2(float x, float y) {
    __half2 h = __floats2half2_rn(x, y);
    return *(uint32_t*)&h;
}
__device__ __forceinline__ uint32_t smem_u32(const void* p) {
    uint32_t a;
    asm("{ .reg .u64 t; cvta.to.shared.u64 t, %1; cvt.u32.u64 %0, t; }"
        : "=r"(a) : "l"(p));
    return a;
}
__device__ __forceinline__ void ldmatrix_x4(uint32_t* r, uint32_t addr) {
    asm volatile("ldmatrix.sync.aligned.m8n8.x4.shared.b16 {%0,%1,%2,%3}, [%4];"
        : "=r"(r[0]), "=r"(r[1]), "=r"(r[2]), "=r"(r[3]) : "r"(addr));
}

// ---------------------------------------------------------------------------
// Prep: fused transposed weights Wt[n=192][k=768], tf32-rounded.
// ---------------------------------------------------------------------------
__global__ __launch_bounds__(256) void wt_kernel(
    const float* __restrict__ Wq,
    const float* __restrict__ Wk,
    const float* __restrict__ Wv)
{
    int i = blockIdx.x * 256 + threadIdx.x;
    int n = i / CC;
    int k = i - n * CC;
    const float* W = (n < 64) ? Wq : (n < 128) ? Wk : Wv;
    g_wt[i] = tf32r(W[k * HH + (n & 63)]);
}

// ---------------------------------------------------------------------------
// QKV via mma.sync tf32 (proven R8). Block = 32 rows x 192 cols.
// ---------------------------------------------------------------------------
__global__ __launch_bounds__(256) void qkv_mma_kernel(const float* __restrict__ x)
{
    __shared__ uint32_t As[32][36];
    __shared__ uint32_t Bs[192][36];

    int tid = threadIdx.x;
    int wid = tid >> 5, lane = tid & 31;
    int g   = lane >> 2, tig = lane & 3;
    int mw  = wid >> 2, nw = wid & 3;
    int mt  = blockIdx.x;

    float acc[6][4];
#pragma unroll
    for (int t = 0; t < 6; ++t)
#pragma unroll
        for (int j = 0; j < 4; ++j) acc[t][j] = 0.f;

    int ar = tid >> 3;
    int ak = (tid & 7) << 2;

    for (int ck = 0; ck < CC; ck += 32) {
        {
            const float4* xr = (const float4*)(x + (size_t)(mt * 32 + ar) * CC + ck + ak);
            float4 v = *xr;
            uint4 t = make_uint4(tf32r(v.x), tf32r(v.y), tf32r(v.z), tf32r(v.w));
            *(uint4*)&As[ar][ak] = t;
        }
#pragma unroll
        for (int j = 0; j < 6; ++j) {
            int idx = tid + j * 256;
            int n  = idx >> 3;
            int kq = (idx & 7) << 2;
            uint4 t = *(const uint4*)&g_wt[(size_t)n * CC + ck + kq];
            *(uint4*)&Bs[n][kq] = t;
        }
        __syncthreads();

#pragma unroll
        for (int ks = 0; ks < 4; ++ks) {
            int k0 = ks << 3;
            uint32_t a[4];
            int r0 = (mw << 4) + g;
            a[0] = As[r0][k0 + tig];
            a[1] = As[r0 + 8][k0 + tig];
            a[2] = As[r0][k0 + tig + 4];
            a[3] = As[r0 + 8][k0 + tig + 4];
#pragma unroll
            for (int t = 0; t < 6; ++t) {
                int n0 = nw * 48 + t * 8;
                uint32_t b[2];
                b[0] = Bs[n0 + g][k0 + tig];
                b[1] = Bs[n0 + g][k0 + tig + 4];
                mma_tf32(acc[t], a, b);
            }
        }
        __syncthreads();
    }

    int row0 = mt * 32 + (mw << 4) + g;
#pragma unroll
    for (int t = 0; t < 6; ++t) {
        int n0  = nw * 48 + t * 8;
        float* G = (n0 < 64) ? g_q : (n0 < 128) ? g_k : g_v;
        int ncol = (n0 & 63) + (tig << 1);
        *(float2*)&G[(size_t)row0 * HH + ncol] = make_float2(acc[t][0], acc[t][1]);
        *(float2*)&G[(size_t)(row0 + 8) * HH + ncol] = make_float2(acc[t][2], acc[t][3]);
    }
}

// ---------------------------------------------------------------------------
// Flash attention on tensor cores (fp16 mma, fp32 accum), kv-split.
// Block = 128 q x 64-key tiles, 8 warps (one per 16 q rows).
// P stays in registers: S c-frags repack directly into PV A-frags.
// ---------------------------------------------------------------------------
__global__ __launch_bounds__(256, 2) void attn_mma_kernel()
{
    int blk = blockIdx.x;                 // 0..255
    int s   = blk & 3;
    int b   = (blk >> 2) & 3;
    int qt  = 15 - (blk >> 4);            // LPT
    int tid = threadIdx.x;
    int wid = tid >> 5, lane = tid & 31;
    int g   = lane >> 2, tig = lane & 3;

    int nkt = 2 * qt + 2;
    int t0  = (s * nkt) >> 2;
    int t1  = ((s + 1) * nkt) >> 2;

    float* po = g_po + ((size_t)(s * BB + b) * TT + qt * BQM) * HH;
    float* pm = g_pm + (size_t)(s * BB + b) * TT + qt * BQM;
    float* pl = g_pl + (size_t)(s * BB + b) * TT + qt * BQM;

    if (t0 == t1) {
        for (int i = tid; i < BQM * HH; i += 256) po[i] = 0.f;
        if (tid < BQM) { pm[tid] = -CUDART_INF_F; pl[tid] = 0.f; }
        return;
    }

    __shared__ __half Qh[128][72];
    __shared__ __half Kh[64][72];
    __shared__ __half Vt[64][72];

    // stage Q tile as fp16
    for (int i = tid; i < 128 * 16; i += 256) {
        int r = i >> 4, c4 = (i & 15) << 2;
        float4 v = *(const float4*)&g_q[(size_t)(b * TT + qt * BQM + r) * HH + c4];
        *(uint32_t*)&Qh[r][c4]     = packh2(v.x, v.y);
        *(uint32_t*)&Qh[r][c4 + 2] = packh2(v.z, v.w);
    }
    __syncthreads();

    // preload Q A-frags via ldmatrix (4 k-steps of 16)
    uint32_t aq[4][4];
    {
        int row = wid * 16 + (lane & 15);
        int cofs = (lane >> 4) << 3;
#pragma unroll
        for (int ks = 0; ks < 4; ++ks)
            ldmatrix_x4(aq[ks], smem_u32(&Qh[row][ks * 16 + cofs]));
    }

    float oc[8][4];
#pragma unroll
    for (int ht = 0; ht < 8; ++ht)
#pragma unroll
        for (int j = 0; j < 4; ++j) oc[ht][j] = 0.f;
    float m0 = -CUDART_INF_F, m1 = -CUDART_INF_F, l0 = 0.f, l1 = 0.f;

    int qrow0 = qt * BQM + wid * 16 + g;   // global q row for c0/c1
    const float scale = 0.125f;

    for (int kt = t0; kt < t1; ++kt) {
        __syncthreads();
        // stage K [key][h] and V^T [h][key] as fp16
        for (int i = tid; i < 64 * 16; i += 256) {
            int r = i >> 4, c4 = (i & 15) << 2;
            float4 v = *(const float4*)&g_k[(size_t)(b * TT + kt * BKN + r) * HH + c4];
            *(uint32_t*)&Kh[r][c4]     = packh2(v.x, v.y);
            *(uint32_t*)&Kh[r][c4 + 2] = packh2(v.z, v.w);
        }
        for (int i = tid; i < 64 * 32; i += 256) {
            int key = i >> 5;
            int h2  = (i & 31) << 1;
            float2 v = *(const float2*)&g_v[(size_t)(b * TT + kt * BKN + key) * HH + h2];
            Vt[h2][key]     = __float2half_rn(v.x);
            Vt[h2 + 1][key] = __float2half_rn(v.y);
        }
        __syncthreads();

        // S = Q K^T
        float c[8][4];
#pragma unroll
        for (int nt = 0; nt < 8; ++nt) {
            c[nt][0] = c[nt][1] = c[nt][2] = c[nt][3] = 0.f;
#pragma unroll
            for (int ks = 0; ks < 4; ++ks) {
                uint32_t b0 = *(const uint32_t*)&Kh[nt * 8 + g][ks * 16 + 2 * tig];
                uint32_t b1 = *(const uint32_t*)&Kh[nt * 8 + g][ks * 16 + 2 * tig + 8];
                mma_f16(c[nt], aq[ks], b0, b1);
            }
        }

        // scale + causal mask
        bool needmask = (kt * BKN + 63 > qt * BQM);
#pragma unroll
        for (int nt = 0; nt < 8; ++nt) {
            int kc = kt * BKN + nt * 8 + 2 * tig;
#pragma unroll
            for (int j = 0; j < 4; ++j) {
                c[nt][j] *= scale;
                if (needmask) {
                    int kg = kc + (j & 1);
                    int qg = (j < 2) ? qrow0 : qrow0 + 8;
                    if (kg > qg) c[nt][j] = -CUDART_INF_F;
                }
            }
        }

        // online softmax (rows g and g+8)
        float rm0 = -CUDART_INF_F, rm1 = -CUDART_INF_F;
#pragma unroll
        for (int nt = 0; nt < 8; ++nt) {
            rm0 = fmaxf(rm0, fmaxf(c[nt][0], c[nt][1]));
            rm1 = fmaxf(rm1, fmaxf(c[nt][2], c[nt][3]));
        }
        rm0 = fmaxf(rm0, __shfl_xor_sync(0xffffffff, rm0, 1));
        rm0 = fmaxf(rm0, __shfl_xor_sync(0xffffffff, rm0, 2));
        rm1 = fmaxf(rm1, __shfl_xor_sync(0xffffffff, rm1, 1));
        rm1 = fmaxf(rm1, __shfl_xor_sync(0xffffffff, rm1, 2));

        float mn0 = fmaxf(m0, rm0), mn1 = fmaxf(m1, rm1);
        float mb0 = (mn0 == -CUDART_INF_F) ? 0.f : mn0;
        float mb1 = (mn1 == -CUDART_INF_F) ? 0.f : mn1;
        float corr0 = __expf(m0 - mb0);
        float corr1 = __expf(m1 - mb1);
        m0 = mn0; m1 = mn1;

        float rs0 = 0.f, rs1 = 0.f;
#pragma unroll
        for (int nt = 0; nt < 8; ++nt) {
            c[nt][0] = __expf(c[nt][0] - mb0);
            c[nt][1] = __expf(c[nt][1] - mb0);
            c[nt][2] = __expf(c[nt][2] - mb1);
            c[nt][3] = __expf(c[nt][3] - mb1);
            rs0 += c[nt][0] + c[nt][1];
            rs1 += c[nt][2] + c[nt][3];
        }
        rs0 += __shfl_xor_sync(0xffffffff, rs0, 1);
        rs0 += __shfl_xor_sync(0xffffffff, rs0, 2);
        rs1 += __shfl_xor_sync(0xffffffff, rs1, 1);
        rs1 += __shfl_xor_sync(0xffffffff, rs1, 2);
        l0 = l0 * corr0 + rs0;
        l1 = l1 * corr1 + rs1;

        // repack P into PV A-frags (register-only, FA2 style)
        uint32_t pa[4][4];
#pragma unroll
        for (int kk = 0; kk < 4; ++kk) {
            pa[kk][0] = packh2(c[2 * kk][0],     c[2 * kk][1]);
            pa[kk][1] = packh2(c[2 * kk][2],     c[2 * kk][3]);
            pa[kk][2] = packh2(c[2 * kk + 1][0], c[2 * kk + 1][1]);
            pa[kk][3] = packh2(c[2 * kk + 1][2], c[2 * kk + 1][3]);
        }

        // O rescale + PV mma
#pragma unroll
        for (int ht = 0; ht < 8; ++ht) {
            oc[ht][0] *= corr0; oc[ht][1] *= corr0;
            oc[ht][2] *= corr1; oc[ht][3] *= corr1;
#pragma unroll
            for (int kk = 0; kk < 4; ++kk) {
                uint32_t b0 = *(const uint32_t*)&Vt[ht * 8 + g][kk * 16 + 2 * tig];
                uint32_t b1 = *(const uint32_t*)&Vt[ht * 8 + g][kk * 16 + 2 * tig + 8];
                mma_f16(oc[ht], pa[kk], b0, b1);
            }
        }
    }

    // write unnormalized partials
    int r0 = wid * 16 + g;
    int r1 = r0 + 8;
#pragma unroll
    for (int ht = 0; ht < 8; ++ht) {
        int col = ht * 8 + 2 * tig;
        *(float2*)&po[(size_t)r0 * HH + col] = make_float2(oc[ht][0], oc[ht][1]);
        *(float2*)&po[(size_t)r1 * HH + col] = make_float2(oc[ht][2], oc[ht][3]);
    }
    if (tig == 0) {
        pm[r0] = m0; pl[r0] = l0;
        pm[r1] = m1; pl[r1] = l1;
    }
}

// ---------------------------------------------------------------------------
// Combine kv-split partials.
// ---------------------------------------------------------------------------
__global__ __launch_bounds__(256) void combine_kernel(float* __restrict__ out)
{
    int idx = blockIdx.x * 256 + threadIdx.x;
    int row = idx >> 6;

    const int MS = BB * TT;
    const int PS = BB * TT * HH;

    float m0 = g_pm[row], m1 = g_pm[MS + row],
          m2 = g_pm[2 * MS + row], m3 = g_pm[3 * MS + row];
    float ms = fmaxf(fmaxf(m0, m1), fmaxf(m2, m3));
    float w0 = __expf(m0 - ms), w1 = __expf(m1 - ms);
    float w2 = __expf(m2 - ms), w3 = __expf(m3 - ms);
    float lt = w0 * g_pl[row] + w1 * g_pl[MS + row]
             + w2 * g_pl[2 * MS + row] + w3 * g_pl[3 * MS + row];
    float ov = w0 * g_po[idx] + w1 * g_po[PS + idx]
             + w2 * g_po[2 * PS + idx] + w3 * g_po[3 * PS + idx];
    out[idx] = ov / lt;
}

extern "C" void kernel_launch(void* const* d_in, const int* in_sizes, int n_in,
                              void* d_out, int out_size)
{
    const float* x  = (const float*)d_in[0];
    const float* Wq = (const float*)d_in[1];
    const float* Wk = (const float*)d_in[2];
    const float* Wv = (const float*)d_in[3];
    float* out = (float*)d_out;

    wt_kernel<<<(3 * HH * CC) / 256, 256>>>(Wq, Wk, Wv);
    qkv_mma_kernel<<<(BB * TT) / 32, 256>>>(x);
    attn_mma_kernel<<<16 * 4 * NS, 256>>>();
    combine_kernel<<<(BB * TT * HH) / 256, 256>>>(out);
}

// round 10
// speedup vs baseline: 3.7792x; 1.6444x over previous
#include <cuda_runtime.h>
#include <math_constants.h>
#include <cuda_fp16.h>
#include <cstdint>

#define BB 4
#define TT 2048
#define CC 768
#define HH 64
#define NS 4
#define BQM 128
#define BKN 64

__device__ __align__(16) __half g_qh[BB * TT * HH];
__device__ __align__(16) __half g_kh[BB * TT * HH];
__device__ __align__(16) __half g_vh[BB * TT * HH];
__device__ __align__(16) __half g_wth[3 * HH * CC];     // fused W^T as half
__device__ __align__(16) float g_po[NS * BB * TT * HH];
__device__ float g_pm[NS * BB * TT];
__device__ float g_pl[NS * BB * TT];

__device__ __forceinline__ void mma_f16(float* c, const uint32_t* a, uint32_t b0, uint32_t b1) {
    asm volatile(
        "mma.sync.aligned.m16n8k16.row.col.f32.f16.f16.f32 "
        "{%0,%1,%2,%3}, {%4,%5,%6,%7}, {%8,%9}, {%0,%1,%2,%3};"
        : "+f"(c[0]), "+f"(c[1]), "+f"(c[2]), "+f"(c[3])
        : "r"(a[0]), "r"(a[1]), "r"(a[2]), "r"(a[3]), "r"(b0), "r"(b1));
}
__device__ __forceinline__ uint32_t packh2(float x, float y) {
    __half2 h = __floats2half2_rn(x, y);
    return *(uint32_t*)&h;
}
__device__ __forceinline__ uint32_t smem_u32(const void* p) {
    uint32_t a;
    asm("{ .reg .u64 t; cvta.to.shared.u64 t, %1; cvt.u32.u64 %0, t; }"
        : "=r"(a) : "l"(p));
    return a;
}
__device__ __forceinline__ void ldmatrix_x4(uint32_t* r, uint32_t addr) {
    asm volatile("ldmatrix.sync.aligned.m8n8.x4.shared.b16 {%0,%1,%2,%3}, [%4];"
        : "=r"(r[0]), "=r"(r[1]), "=r"(r[2]), "=r"(r[3]) : "r"(addr));
}
__device__ __forceinline__ void ldmatrix_x2(uint32_t& r0, uint32_t& r1, uint32_t addr) {
    asm volatile("ldmatrix.sync.aligned.m8n8.x2.shared.b16 {%0,%1}, [%2];"
        : "=r"(r0), "=r"(r1) : "r"(addr));
}
__device__ __forceinline__ void ldmatrix_x2t(uint32_t& r0, uint32_t& r1, uint32_t addr) {
    asm volatile("ldmatrix.sync.aligned.m8n8.x2.trans.shared.b16 {%0,%1}, [%2];"
        : "=r"(r0), "=r"(r1) : "r"(addr));
}
__device__ __forceinline__ float ex2f(float x) {
    float r; asm("ex2.approx.ftz.f32 %0, %1;" : "=f"(r) : "f"(x)); return r;
}
#define CP_ASYNC16(dst, src) \
    asm volatile("cp.async.cg.shared.global [%0], [%1], 16;" :: "r"(dst), "l"(src))
#define CP_COMMIT() asm volatile("cp.async.commit_group;" ::: "memory")
#define CP_WAIT0()  asm volatile("cp.async.wait_group 0;" ::: "memory")

// ---------------------------------------------------------------------------
// Prep: fused transposed weights Wt[n=192][k=768] as half.
// ---------------------------------------------------------------------------
__global__ __launch_bounds__(256) void wt_kernel(
    const float* __restrict__ Wq,
    const float* __restrict__ Wk,
    const float* __restrict__ Wv)
{
    int i = blockIdx.x * 256 + threadIdx.x;     // < 192*768
    int n = i / CC;
    int k = i - n * CC;
    const float* W = (n < 64) ? Wq : (n < 128) ? Wk : Wv;
    g_wth[i] = __float2half_rn(W[k * HH + (n & 63)]);
}

// ---------------------------------------------------------------------------
// QKV via fp16 mma.sync m16n8k16. Block = 32 rows x 192 cols (Q|K|V).
// 8 warps in 2(m) x 4(n); warp tile m16 x n48. ldmatrix for A and B frags.
// Outputs written directly as fp16.
// ---------------------------------------------------------------------------
__global__ __launch_bounds__(256) void qkv_mma_kernel(const float* __restrict__ x)
{
    __shared__ __half As[32][40];
    __shared__ __half Bs[192][40];

    int tid = threadIdx.x;
    int wid = tid >> 5, lane = tid & 31;
    int g   = lane >> 2, tig = lane & 3;
    int mw  = wid >> 2, nw = wid & 3;
    int mt  = blockIdx.x;

    float acc[6][4];
#pragma unroll
    for (int t = 0; t < 6; ++t)
#pragma unroll
        for (int j = 0; j < 4; ++j) acc[t][j] = 0.f;

    // frag smem addresses (lane-baked)
    uint32_t addrA = smem_u32(&As[(mw << 4) + (lane & 15)][(lane >> 4) << 3]);
    uint32_t addrB = smem_u32(&Bs[nw * 48 + (lane & 7)][((lane >> 3) & 1) << 3]);

    int ar = tid >> 3;                // 0..31
    int akq = (tid & 7) << 2;         // 0,4,..28 (floats)

    for (int ck = 0; ck < CC; ck += 32) {
        // stage A: float4 -> 4 halves
        {
            float4 v = *(const float4*)(x + (size_t)(mt * 32 + ar) * CC + ck + akq);
            uint2 t = make_uint2(packh2(v.x, v.y), packh2(v.z, v.w));
            *(uint2*)&As[ar][akq] = t;
        }
        // stage B: copy 16B chunks of g_wth
#pragma unroll
        for (int j = 0; j < 3; ++j) {
            int u = tid + j * 256;    // < 768
            int n  = u >> 2;
            int k8 = (u & 3) << 3;
            uint4 t = *(const uint4*)&g_wth[(size_t)n * CC + ck + k8];
            *(uint4*)&Bs[n][k8] = t;
        }
        __syncthreads();

#pragma unroll
        for (int ks = 0; ks < 2; ++ks) {
            uint32_t a[4];
            ldmatrix_x4(a, addrA + ks * 32);                 // +16 halves
#pragma unroll
            for (int t = 0; t < 6; ++t) {
                uint32_t b0, b1;
                ldmatrix_x2(b0, b1, addrB + t * (8 * 80) + ks * 32);
                mma_f16(acc[t], a, b0, b1);
            }
        }
        __syncthreads();
    }

    int row0 = mt * 32 + (mw << 4) + g;
#pragma unroll
    for (int t = 0; t < 6; ++t) {
        int n0  = nw * 48 + t * 8;
        __half* G = (n0 < 64) ? g_qh : (n0 < 128) ? g_kh : g_vh;
        int ncol = (n0 & 63) + (tig << 1);
        *(uint32_t*)&G[(size_t)row0 * HH + ncol] = packh2(acc[t][0], acc[t][1]);
        *(uint32_t*)&G[(size_t)(row0 + 8) * HH + ncol] = packh2(acc[t][2], acc[t][3]);
    }
}

// ---------------------------------------------------------------------------
// Flash attention: fp16 mma, cp.async double-buffered K/V, ldmatrix B-frags,
// exp2-domain softmax. Block = 128 q; kv-split x4.
// ---------------------------------------------------------------------------
__global__ __launch_bounds__(256, 2) void attn_mma_kernel()
{
    int blk = blockIdx.x;
    int s   = blk & 3;
    int b   = (blk >> 2) & 3;
    int qt  = 15 - (blk >> 4);
    int tid = threadIdx.x;
    int wid = tid >> 5, lane = tid & 31;
    int g   = lane >> 2, tig = lane & 3;

    int nkt = 2 * qt + 2;
    int t0  = (s * nkt) >> 2;
    int t1  = ((s + 1) * nkt) >> 2;

    float* po = g_po + ((size_t)(s * BB + b) * TT + qt * BQM) * HH;
    float* pm = g_pm + (size_t)(s * BB + b) * TT + qt * BQM;
    float* pl = g_pl + (size_t)(s * BB + b) * TT + qt * BQM;

    if (t0 == t1) {
        for (int i = tid; i < BQM * HH; i += 256) po[i] = 0.f;
        if (tid < BQM) { pm[tid] = -CUDART_INF_F; pl[tid] = 0.f; }
        return;
    }

    __shared__ __half Qh[128][72];
    __shared__ __half Kh[2][64][72];
    __shared__ __half Vh[2][64][72];

    // stage Q + first K/V tile via cp.async
    {
        const __half* qsrc = g_qh + (size_t)(b * TT + qt * BQM) * HH;
#pragma unroll
        for (int i = 0; i < 4; ++i) {
            int u = tid + i * 256;            // < 1024
            int r = u >> 3, c = (u & 7) << 3;
            CP_ASYNC16(smem_u32(&Qh[r][c]), qsrc + (size_t)r * HH + c);
        }
        const __half* ks = g_kh + (size_t)(b * TT + t0 * BKN) * HH;
        const __half* vs = g_vh + (size_t)(b * TT + t0 * BKN) * HH;
#pragma unroll
        for (int i = 0; i < 2; ++i) {
            int u = tid + i * 256;            // < 512
            int r = u >> 3, c = (u & 7) << 3;
            CP_ASYNC16(smem_u32(&Kh[0][r][c]), ks + (size_t)r * HH + c);
            CP_ASYNC16(smem_u32(&Vh[0][r][c]), vs + (size_t)r * HH + c);
        }
        CP_COMMIT();
        CP_WAIT0();
    }
    __syncthreads();

    // preload Q A-frags
    uint32_t aq[4][4];
    {
        uint32_t addrQ = smem_u32(&Qh[wid * 16 + (lane & 15)][(lane >> 4) << 3]);
#pragma unroll
        for (int ks = 0; ks < 4; ++ks)
            ldmatrix_x4(aq[ks], addrQ + ks * 32);
    }

    uint32_t aKb = smem_u32(&Kh[0][lane & 7][((lane >> 3) & 1) << 3]);
    uint32_t aVb = smem_u32(&Vh[0][lane & 15][0]);
    const uint32_t bufstride = 64 * 72 * 2;   // bytes per K/V buffer

    float oc[8][4];
#pragma unroll
    for (int ht = 0; ht < 8; ++ht)
#pragma unroll
        for (int j = 0; j < 4; ++j) oc[ht][j] = 0.f;
    float m0 = -CUDART_INF_F, m1 = -CUDART_INF_F, l0 = 0.f, l1 = 0.f;

    int qrow0 = qt * BQM + wid * 16 + g;
    const float SCL2 = 0.125f * 1.4426950408889634f;   // scale * log2(e)

    int buf = 0;
    for (int kt = t0; kt < t1; ++kt) {
        // prefetch next K/V tile into the other buffer
        if (kt + 1 < t1) {
            const __half* ks = g_kh + (size_t)(b * TT + (kt + 1) * BKN) * HH;
            const __half* vs = g_vh + (size_t)(b * TT + (kt + 1) * BKN) * HH;
            int nb = buf ^ 1;
#pragma unroll
            for (int i = 0; i < 2; ++i) {
                int u = tid + i * 256;
                int r = u >> 3, c = (u & 7) << 3;
                CP_ASYNC16(smem_u32(&Kh[nb][r][c]), ks + (size_t)r * HH + c);
                CP_ASYNC16(smem_u32(&Vh[nb][r][c]), vs + (size_t)r * HH + c);
            }
            CP_COMMIT();
        }

        uint32_t addrK = aKb + buf * bufstride;
        uint32_t addrV = aVb + buf * bufstride;

        // S = Q K^T
        float c[8][4];
#pragma unroll
        for (int nt = 0; nt < 8; ++nt) {
            c[nt][0] = c[nt][1] = c[nt][2] = c[nt][3] = 0.f;
#pragma unroll
            for (int ks = 0; ks < 4; ++ks) {
                uint32_t b0, b1;
                ldmatrix_x2(b0, b1, addrK + nt * (8 * 144) + ks * 32);
                mma_f16(c[nt], aq[ks], b0, b1);
            }
        }

        // scale into log2 domain + causal mask
        bool needmask = (kt * BKN + 63 > qt * BQM);
#pragma unroll
        for (int nt = 0; nt < 8; ++nt) {
            int kc = kt * BKN + nt * 8 + 2 * tig;
#pragma unroll
            for (int j = 0; j < 4; ++j) {
                c[nt][j] *= SCL2;
                if (needmask) {
                    int kg = kc + (j & 1);
                    int qg = (j < 2) ? qrow0 : qrow0 + 8;
                    if (kg > qg) c[nt][j] = -CUDART_INF_F;
                }
            }
        }

        // online softmax (log2 domain)
        float rm0 = -CUDART_INF_F, rm1 = -CUDART_INF_F;
#pragma unroll
        for (int nt = 0; nt < 8; ++nt) {
            rm0 = fmaxf(rm0, fmaxf(c[nt][0], c[nt][1]));
            rm1 = fmaxf(rm1, fmaxf(c[nt][2], c[nt][3]));
        }
        rm0 = fmaxf(rm0, __shfl_xor_sync(0xffffffff, rm0, 1));
        rm0 = fmaxf(rm0, __shfl_xor_sync(0xffffffff, rm0, 2));
        rm1 = fmaxf(rm1, __shfl_xor_sync(0xffffffff, rm1, 1));
        rm1 = fmaxf(rm1, __shfl_xor_sync(0xffffffff, rm1, 2));

        float mn0 = fmaxf(m0, rm0), mn1 = fmaxf(m1, rm1);
        float mb0 = (mn0 == -CUDART_INF_F) ? 0.f : mn0;
        float mb1 = (mn1 == -CUDART_INF_F) ? 0.f : mn1;
        float corr0 = ex2f(m0 - mb0);
        float corr1 = ex2f(m1 - mb1);
        m0 = mn0; m1 = mn1;

        float rs0 = 0.f, rs1 = 0.f;
#pragma unroll
        for (int nt = 0; nt < 8; ++nt) {
            c[nt][0] = ex2f(c[nt][0] - mb0);
            c[nt][1] = ex2f(c[nt][1] - mb0);
            c[nt][2] = ex2f(c[nt][2] - mb1);
            c[nt][3] = ex2f(c[nt][3] - mb1);
            rs0 += c[nt][0] + c[nt][1];
            rs1 += c[nt][2] + c[nt][3];
        }
        rs0 += __shfl_xor_sync(0xffffffff, rs0, 1);
        rs0 += __shfl_xor_sync(0xffffffff, rs0, 2);
        rs1 += __shfl_xor_sync(0xffffffff, rs1, 1);
        rs1 += __shfl_xor_sync(0xffffffff, rs1, 2);
        l0 = l0 * corr0 + rs0;
        l1 = l1 * corr1 + rs1;

        // repack P into PV A-frags (register-only)
        uint32_t pa[4][4];
#pragma unroll
        for (int kk = 0; kk < 4; ++kk) {
            pa[kk][0] = packh2(c[2 * kk][0],     c[2 * kk][1]);
            pa[kk][1] = packh2(c[2 * kk][2],     c[2 * kk][3]);
            pa[kk][2] = packh2(c[2 * kk + 1][0], c[2 * kk + 1][1]);
            pa[kk][3] = packh2(c[2 * kk + 1][2], c[2 * kk + 1][3]);
        }

        // O rescale + PV mma (V B-frags via ldmatrix.trans from natural layout)
#pragma unroll
        for (int ht = 0; ht < 8; ++ht) {
            oc[ht][0] *= corr0; oc[ht][1] *= corr0;
            oc[ht][2] *= corr1; oc[ht][3] *= corr1;
#pragma unroll
            for (int kk = 0; kk < 4; ++kk) {
                uint32_t b0, b1;
                ldmatrix_x2t(b0, b1, addrV + kk * (16 * 144) + ht * 16);
                mma_f16(oc[ht], pa[kk], b0, b1);
            }
        }

        if (kt + 1 < t1) CP_WAIT0();
        __syncthreads();
        buf ^= 1;
    }

    // write unnormalized partials (m in log2 domain)
    int r0 = wid * 16 + g;
    int r1 = r0 + 8;
#pragma unroll
    for (int ht = 0; ht < 8; ++ht) {
        int col = ht * 8 + 2 * tig;
        *(float2*)&po[(size_t)r0 * HH + col] = make_float2(oc[ht][0], oc[ht][1]);
        *(float2*)&po[(size_t)r1 * HH + col] = make_float2(oc[ht][2], oc[ht][3]);
    }
    if (tig == 0) {
        pm[r0] = m0; pl[r0] = l0;
        pm[r1] = m1; pl[r1] = l1;
    }
}

// ---------------------------------------------------------------------------
// Combine kv-split partials (float4 per thread, log2-domain weights).
// ---------------------------------------------------------------------------
__global__ __launch_bounds__(256) void combine_kernel(float* __restrict__ out)
{
    int i4  = blockIdx.x * 256 + threadIdx.x;   // float4 index < 131072
    int row = i4 >> 4;

    const int MS  = BB * TT;
    const int PS4 = (BB * TT * HH) / 4;

    float m0 = g_pm[row], m1 = g_pm[MS + row],
          m2 = g_pm[2 * MS + row], m3 = g_pm[3 * MS + row];
    float ms = fmaxf(fmaxf(m0, m1), fmaxf(m2, m3));
    float w0 = ex2f(m0 - ms), w1 = ex2f(m1 - ms);
    float w2 = ex2f(m2 - ms), w3 = ex2f(m3 - ms);
    float lt = w0 * g_pl[row] + w1 * g_pl[MS + row]
             + w2 * g_pl[2 * MS + row] + w3 * g_pl[3 * MS + row];
    float inv = 1.f / lt;

    const float4* p4 = (const float4*)g_po;
    float4 a = p4[i4], b = p4[PS4 + i4], c = p4[2 * PS4 + i4], d = p4[3 * PS4 + i4];
    float4 o;
    o.x = (w0 * a.x + w1 * b.x + w2 * c.x + w3 * d.x) * inv;
    o.y = (w0 * a.y + w1 * b.y + w2 * c.y + w3 * d.y) * inv;
    o.z = (w0 * a.z + w1 * b.z + w2 * c.z + w3 * d.z) * inv;
    o.w = (w0 * a.w + w1 * b.w + w2 * c.w + w3 * d.w) * inv;
    ((float4*)out)[i4] = o;
}

extern "C" void kernel_launch(void* const* d_in, const int* in_sizes, int n_in,
                              void* d_out, int out_size)
{
    const float* x  = (const float*)d_in[0];
    const float* Wq = (const float*)d_in[1];
    const float* Wk = (const float*)d_in[2];
    const float* Wv = (const float*)d_in[3];
    float* out = (float*)d_out;

    wt_kernel<<<(3 * HH * CC) / 256, 256>>>(Wq, Wk, Wv);
    qkv_mma_kernel<<<(BB * TT) / 32, 256>>>(x);
    attn_mma_kernel<<<16 * 4 * NS, 256>>>();
    combine_kernel<<<(BB * TT * HH) / 4 / 256, 256>>>(out);
}

// round 11
// speedup vs baseline: 3.9694x; 1.0503x over previous
#include <cuda_runtime.h>
#include <math_constants.h>
#include <cuda_fp16.h>
#include <cstdint>

#define BB 4
#define TT 2048
#define CC 768
#define HH 64
#define NS 4
#define BQM 128
#define BKN 64

__device__ __align__(16) __half g_qh[BB * TT * HH];
__device__ __align__(16) __half g_kh[BB * TT * HH];
__device__ __align__(16) __half g_vh[BB * TT * HH];
__device__ __align__(16) __half g_wth[3 * HH * CC];
__device__ __align__(16) __half g_poh[NS * BB * TT * HH];
__device__ float g_pm[NS * BB * TT];
__device__ float g_pl[NS * BB * TT];

__device__ __forceinline__ void mma_f16(float* c, const uint32_t* a, uint32_t b0, uint32_t b1) {
    asm volatile(
        "mma.sync.aligned.m16n8k16.row.col.f32.f16.f16.f32 "
        "{%0,%1,%2,%3}, {%4,%5,%6,%7}, {%8,%9}, {%0,%1,%2,%3};"
        : "+f"(c[0]), "+f"(c[1]), "+f"(c[2]), "+f"(c[3])
        : "r"(a[0]), "r"(a[1]), "r"(a[2]), "r"(a[3]), "r"(b0), "r"(b1));
}
__device__ __forceinline__ uint32_t packh2(float x, float y) {
    __half2 h = __floats2half2_rn(x, y);
    return *(uint32_t*)&h;
}
__device__ __forceinline__ uint32_t smem_u32(const void* p) {
    uint32_t a;
    asm("{ .reg .u64 t; cvta.to.shared.u64 t, %1; cvt.u32.u64 %0, t; }"
        : "=r"(a) : "l"(p));
    return a;
}
__device__ __forceinline__ void ldmatrix_x4(uint32_t* r, uint32_t addr) {
    asm volatile("ldmatrix.sync.aligned.m8n8.x4.shared.b16 {%0,%1,%2,%3}, [%4];"
        : "=r"(r[0]), "=r"(r[1]), "=r"(r[2]), "=r"(r[3]) : "r"(addr));
}
__device__ __forceinline__ void ldmatrix_x2(uint32_t& r0, uint32_t& r1, uint32_t addr) {
    asm volatile("ldmatrix.sync.aligned.m8n8.x2.shared.b16 {%0,%1}, [%2];"
        : "=r"(r0), "=r"(r1) : "r"(addr));
}
__device__ __forceinline__ void ldmatrix_x2t(uint32_t& r0, uint32_t& r1, uint32_t addr) {
    asm volatile("ldmatrix.sync.aligned.m8n8.x2.trans.shared.b16 {%0,%1}, [%2];"
        : "=r"(r0), "=r"(r1) : "r"(addr));
}
__device__ __forceinline__ float ex2f(float x) {
    float r; asm("ex2.approx.ftz.f32 %0, %1;" : "=f"(r) : "f"(x)); return r;
}
#define CP_ASYNC16(dst, src) \
    asm volatile("cp.async.cg.shared.global [%0], [%1], 16;" :: "r"(dst), "l"(src))
#define CP_COMMIT() asm volatile("cp.async.commit_group;" ::: "memory")
#define CP_WAIT0()  asm volatile("cp.async.wait_group 0;" ::: "memory")

// ---------------------------------------------------------------------------
// Prep: fused transposed weights Wt[n=192][k=768] as half.
// ---------------------------------------------------------------------------
__global__ __launch_bounds__(256) void wt_kernel(
    const float* __restrict__ Wq,
    const float* __restrict__ Wk,
    const float* __restrict__ Wv)
{
    int i = blockIdx.x * 256 + threadIdx.x;
    int n = i / CC;
    int k = i - n * CC;
    const float* W = (n < 64) ? Wq : (n < 128) ? Wk : Wv;
    g_wth[i] = __float2half_rn(W[k * HH + (n & 63)]);
}

// ---------------------------------------------------------------------------
// QKV via fp16 mma.sync, software-pipelined staging (double smem buffer +
// register prefetch, single barrier per iteration).
// ---------------------------------------------------------------------------
__global__ __launch_bounds__(256) void qkv_mma_kernel(const float* __restrict__ x)
{
    __shared__ __half As[2][32][40];
    __shared__ __half Bs[2][192][40];
    const uint32_t ABUF = 32 * 40 * 2;     // bytes per A buffer
    const uint32_t BBUF = 192 * 40 * 2;

    int tid = threadIdx.x;
    int wid = tid >> 5, lane = tid & 31;
    int g   = lane >> 2, tig = lane & 3;
    int mw  = wid >> 2, nw = wid & 3;
    int mt  = blockIdx.x;

    float acc[6][4];
#pragma unroll
    for (int t = 0; t < 6; ++t)
#pragma unroll
        for (int j = 0; j < 4; ++j) acc[t][j] = 0.f;

    uint32_t addrA = smem_u32(&As[0][(mw << 4) + (lane & 15)][(lane >> 4) << 3]);
    uint32_t addrB = smem_u32(&Bs[0][nw * 48 + (lane & 7)][((lane >> 3) & 1) << 3]);

    int ar  = tid >> 3;
    int akq = (tid & 7) << 2;
    const float* xrow = x + (size_t)(mt * 32 + ar) * CC + akq;

    // prefetch chunk 0
    float4 va = *(const float4*)xrow;
    uint4 vb[3];
#pragma unroll
    for (int j = 0; j < 3; ++j) {
        int u = tid + j * 256;
        int n = u >> 2, k8 = (u & 3) << 3;
        vb[j] = *(const uint4*)&g_wth[(size_t)n * CC + k8];
    }

    for (int it = 0; it < CC / 32; ++it) {
        int buf = it & 1;
        // store staged regs
        *(uint2*)&As[buf][ar][akq] = make_uint2(packh2(va.x, va.y), packh2(va.z, va.w));
#pragma unroll
        for (int j = 0; j < 3; ++j) {
            int u = tid + j * 256;
            int n = u >> 2, k8 = (u & 3) << 3;
            *(uint4*)&Bs[buf][n][k8] = vb[j];
        }
        __syncthreads();

        // prefetch next chunk (LDG in flight during compute)
        if (it + 1 < CC / 32) {
            int ck = (it + 1) * 32;
            va = *(const float4*)(xrow + ck);
#pragma unroll
            for (int j = 0; j < 3; ++j) {
                int u = tid + j * 256;
                int n = u >> 2, k8 = (u & 3) << 3;
                vb[j] = *(const uint4*)&g_wth[(size_t)n * CC + ck + k8];
            }
        }

        uint32_t aA = addrA + buf * ABUF;
        uint32_t aB = addrB + buf * BBUF;
#pragma unroll
        for (int ks = 0; ks < 2; ++ks) {
            uint32_t a[4];
            ldmatrix_x4(a, aA + ks * 32);
#pragma unroll
            for (int t = 0; t < 6; ++t) {
                uint32_t b0, b1;
                ldmatrix_x2(b0, b1, aB + t * (8 * 80) + ks * 32);
                mma_f16(acc[t], a, b0, b1);
            }
        }
    }

    int row0 = mt * 32 + (mw << 4) + g;
#pragma unroll
    for (int t = 0; t < 6; ++t) {
        int n0  = nw * 48 + t * 8;
        __half* G = (n0 < 64) ? g_qh : (n0 < 128) ? g_kh : g_vh;
        int ncol = (n0 & 63) + (tig << 1);
        *(uint32_t*)&G[(size_t)row0 * HH + ncol] = packh2(acc[t][0], acc[t][1]);
        *(uint32_t*)&G[(size_t)(row0 + 8) * HH + ncol] = packh2(acc[t][2], acc[t][3]);
    }
}

// ---------------------------------------------------------------------------
// Flash attention (fp16 mma, cp.async double-buffer, exp2 softmax, kv-split).
// Partials stored as fp16.
// ---------------------------------------------------------------------------
__global__ __launch_bounds__(256, 2) void attn_mma_kernel()
{
    int blk = blockIdx.x;
    int s   = blk & 3;
    int b   = (blk >> 2) & 3;
    int qt  = 15 - (blk >> 4);
    int tid = threadIdx.x;
    int wid = tid >> 5, lane = tid & 31;
    int g   = lane >> 2, tig = lane & 3;

    int nkt = 2 * qt + 2;
    int t0  = (s * nkt) >> 2;
    int t1  = ((s + 1) * nkt) >> 2;

    __half* po = g_poh + ((size_t)(s * BB + b) * TT + qt * BQM) * HH;
    float* pm = g_pm + (size_t)(s * BB + b) * TT + qt * BQM;
    float* pl = g_pl + (size_t)(s * BB + b) * TT + qt * BQM;

    if (t0 == t1) {
        for (int i = tid; i < (BQM * HH) / 2; i += 256) ((uint32_t*)po)[i] = 0;
        if (tid < BQM) { pm[tid] = -CUDART_INF_F; pl[tid] = 0.f; }
        return;
    }

    __shared__ __half Qh[128][72];
    __shared__ __half Kh[2][64][72];
    __shared__ __half Vh[2][64][72];

    {
        const __half* qsrc = g_qh + (size_t)(b * TT + qt * BQM) * HH;
#pragma unroll
        for (int i = 0; i < 4; ++i) {
            int u = tid + i * 256;
            int r = u >> 3, c = (u & 7) << 3;
            CP_ASYNC16(smem_u32(&Qh[r][c]), qsrc + (size_t)r * HH + c);
        }
        const __half* ks = g_kh + (size_t)(b * TT + t0 * BKN) * HH;
        const __half* vs = g_vh + (size_t)(b * TT + t0 * BKN) * HH;
#pragma unroll
        for (int i = 0; i < 2; ++i) {
            int u = tid + i * 256;
            int r = u >> 3, c = (u & 7) << 3;
            CP_ASYNC16(smem_u32(&Kh[0][r][c]), ks + (size_t)r * HH + c);
            CP_ASYNC16(smem_u32(&Vh[0][r][c]), vs + (size_t)r * HH + c);
        }
        CP_COMMIT();
        CP_WAIT0();
    }
    __syncthreads();

    uint32_t aq[4][4];
    {
        uint32_t addrQ = smem_u32(&Qh[wid * 16 + (lane & 15)][(lane >> 4) << 3]);
#pragma unroll
        for (int ks = 0; ks < 4; ++ks)
            ldmatrix_x4(aq[ks], addrQ + ks * 32);
    }

    uint32_t aKb = smem_u32(&Kh[0][lane & 7][((lane >> 3) & 1) << 3]);
    uint32_t aVb = smem_u32(&Vh[0][lane & 15][0]);
    const uint32_t bufstride = 64 * 72 * 2;

    float oc[8][4];
#pragma unroll
    for (int ht = 0; ht < 8; ++ht)
#pragma unroll
        for (int j = 0; j < 4; ++j) oc[ht][j] = 0.f;
    float m0 = -CUDART_INF_F, m1 = -CUDART_INF_F, l0 = 0.f, l1 = 0.f;

    int qrow0 = qt * BQM + wid * 16 + g;
    const float SCL2 = 0.125f * 1.4426950408889634f;

    int buf = 0;
    for (int kt = t0; kt < t1; ++kt) {
        if (kt + 1 < t1) {
            const __half* ks = g_kh + (size_t)(b * TT + (kt + 1) * BKN) * HH;
            const __half* vs = g_vh + (size_t)(b * TT + (kt + 1) * BKN) * HH;
            int nb = buf ^ 1;
#pragma unroll
            for (int i = 0; i < 2; ++i) {
                int u = tid + i * 256;
                int r = u >> 3, c = (u & 7) << 3;
                CP_ASYNC16(smem_u32(&Kh[nb][r][c]), ks + (size_t)r * HH + c);
                CP_ASYNC16(smem_u32(&Vh[nb][r][c]), vs + (size_t)r * HH + c);
            }
            CP_COMMIT();
        }

        uint32_t addrK = aKb + buf * bufstride;
        uint32_t addrV = aVb + buf * bufstride;

        float c[8][4];
#pragma unroll
        for (int nt = 0; nt < 8; ++nt) {
            c[nt][0] = c[nt][1] = c[nt][2] = c[nt][3] = 0.f;
#pragma unroll
            for (int ks = 0; ks < 4; ++ks) {
                uint32_t b0, b1;
                ldmatrix_x2(b0, b1, addrK + nt * (8 * 144) + ks * 32);
                mma_f16(c[nt], aq[ks], b0, b1);
            }
        }

        bool needmask = (kt * BKN + 63 > qt * BQM);
#pragma unroll
        for (int nt = 0; nt < 8; ++nt) {
            int kc = kt * BKN + nt * 8 + 2 * tig;
#pragma unroll
            for (int j = 0; j < 4; ++j) {
                c[nt][j] *= SCL2;
                if (needmask) {
                    int kg = kc + (j & 1);
                    int qg = (j < 2) ? qrow0 : qrow0 + 8;
                    if (kg > qg) c[nt][j] = -CUDART_INF_F;
                }
            }
        }

        float rm0 = -CUDART_INF_F, rm1 = -CUDART_INF_F;
#pragma unroll
        for (int nt = 0; nt < 8; ++nt) {
            rm0 = fmaxf(rm0, fmaxf(c[nt][0], c[nt][1]));
            rm1 = fmaxf(rm1, fmaxf(c[nt][2], c[nt][3]));
        }
        rm0 = fmaxf(rm0, __shfl_xor_sync(0xffffffff, rm0, 1));
        rm0 = fmaxf(rm0, __shfl_xor_sync(0xffffffff, rm0, 2));
        rm1 = fmaxf(rm1, __shfl_xor_sync(0xffffffff, rm1, 1));
        rm1 = fmaxf(rm1, __shfl_xor_sync(0xffffffff, rm1, 2));

        float mn0 = fmaxf(m0, rm0), mn1 = fmaxf(m1, rm1);
        float mb0 = (mn0 == -CUDART_INF_F) ? 0.f : mn0;
        float mb1 = (mn1 == -CUDART_INF_F) ? 0.f : mn1;
        float corr0 = ex2f(m0 - mb0);
        float corr1 = ex2f(m1 - mb1);
        m0 = mn0; m1 = mn1;

        float rs0 = 0.f, rs1 = 0.f;
#pragma unroll
        for (int nt = 0; nt < 8; ++nt) {
            c[nt][0] = ex2f(c[nt][0] - mb0);
            c[nt][1] = ex2f(c[nt][1] - mb0);
            c[nt][2] = ex2f(c[nt][2] - mb1);
            c[nt][3] = ex2f(c[nt][3] - mb1);
            rs0 += c[nt][0] + c[nt][1];
            rs1 += c[nt][2] + c[nt][3];
        }
        rs0 += __shfl_xor_sync(0xffffffff, rs0, 1);
        rs0 += __shfl_xor_sync(0xffffffff, rs0, 2);
        rs1 += __shfl_xor_sync(0xffffffff, rs1, 1);
        rs1 += __shfl_xor_sync(0xffffffff, rs1, 2);
        l0 = l0 * corr0 + rs0;
        l1 = l1 * corr1 + rs1;

        uint32_t pa[4][4];
#pragma unroll
        for (int kk = 0; kk < 4; ++kk) {
            pa[kk][0] = packh2(c[2 * kk][0],     c[2 * kk][1]);
            pa[kk][1] = packh2(c[2 * kk][2],     c[2 * kk][3]);
            pa[kk][2] = packh2(c[2 * kk + 1][0], c[2 * kk + 1][1]);
            pa[kk][3] = packh2(c[2 * kk + 1][2], c[2 * kk + 1][3]);
        }

#pragma unroll
        for (int ht = 0; ht < 8; ++ht) {
            oc[ht][0] *= corr0; oc[ht][1] *= corr0;
            oc[ht][2] *= corr1; oc[ht][3] *= corr1;
#pragma unroll
            for (int kk = 0; kk < 4; ++kk) {
                uint32_t b0, b1;
                ldmatrix_x2t(b0, b1, addrV + kk * (16 * 144) + ht * 16);
                mma_f16(oc[ht], pa[kk], b0, b1);
            }
        }

        if (kt + 1 < t1) CP_WAIT0();
        __syncthreads();
        buf ^= 1;
    }

    int r0 = wid * 16 + g;
    int r1 = r0 + 8;
#pragma unroll
    for (int ht = 0; ht < 8; ++ht) {
        int col = ht * 8 + 2 * tig;
        *(uint32_t*)&po[(size_t)r0 * HH + col] = packh2(oc[ht][0], oc[ht][1]);
        *(uint32_t*)&po[(size_t)r1 * HH + col] = packh2(oc[ht][2], oc[ht][3]);
    }
    if (tig == 0) {
        pm[r0] = m0; pl[r0] = l0;
        pm[r1] = m1; pl[r1] = l1;
    }
}

// ---------------------------------------------------------------------------
// Combine kv-split partials (fp16 partials, 4 elements per thread).
// ---------------------------------------------------------------------------
__global__ __launch_bounds__(256) void combine_kernel(float* __restrict__ out)
{
    int i4  = blockIdx.x * 256 + threadIdx.x;   // group of 4 elems
    int row = i4 >> 4;

    const int MS = BB * TT;
    const int PS = BB * TT * HH;

    float m0 = g_pm[row], m1 = g_pm[MS + row],
          m2 = g_pm[2 * MS + row], m3 = g_pm[3 * MS + row];
    float ms = fmaxf(fmaxf(m0, m1), fmaxf(m2, m3));
    float w0 = ex2f(m0 - ms), w1 = ex2f(m1 - ms);
    float w2 = ex2f(m2 - ms), w3 = ex2f(m3 - ms);
    float lt = w0 * g_pl[row] + w1 * g_pl[MS + row]
             + w2 * g_pl[2 * MS + row] + w3 * g_pl[3 * MS + row];
    float inv = 1.f / lt;

    float o[4] = {0.f, 0.f, 0.f, 0.f};
    float w[4] = {w0, w1, w2, w3};
#pragma unroll
    for (int s = 0; s < 4; ++s) {
        uint2 u = *(const uint2*)&g_poh[(size_t)s * PS + (size_t)i4 * 4];
        float2 p0 = __half22float2(*(const __half2*)&u.x);
        float2 p1 = __half22float2(*(const __half2*)&u.y);
        o[0] += w[s] * p0.x; o[1] += w[s] * p0.y;
        o[2] += w[s] * p1.x; o[3] += w[s] * p1.y;
    }
    float4 r = make_float4(o[0] * inv, o[1] * inv, o[2] * inv, o[3] * inv);
    ((float4*)out)[i4] = r;
}

extern "C" void kernel_launch(void* const* d_in, const int* in_sizes, int n_in,
                              void* d_out, int out_size)
{
    const float* x  = (const float*)d_in[0];
    const float* Wq = (const float*)d_in[1];
    const float* Wk = (const float*)d_in[2];
    const float* Wv = (const float*)d_in[3];
    float* out = (float*)d_out;

    wt_kernel<<<(3 * HH * CC) / 256, 256>>>(Wq, Wk, Wv);
    qkv_mma_kernel<<<(BB * TT) / 32, 256>>>(x);
    attn_mma_kernel<<<16 * 4 * NS, 256>>>();
    combine_kernel<<<(BB * TT * HH) / 4 / 256, 256>>>(out);
}

// round 12
// speedup vs baseline: 4.0015x; 1.0081x over previous
#include <cuda_runtime.h>
#include <math_constants.h>
#include <cuda_fp16.h>
#include <cstdint>

#define BB 4
#define TT 2048
#define CC 768
#define HH 64
#define NS 4
#define BQM 128
#define BKN 64

__device__ __align__(16) __half g_qh[BB * TT * HH];
__device__ __align__(16) __half g_kh[BB * TT * HH];
__device__ __align__(16) __half g_vh[BB * TT * HH];
__device__ __align__(16) __half g_wth[3 * HH * CC];
__device__ __align__(16) __half g_poh[NS * BB * TT * HH];
__device__ float g_pm[NS * BB * TT];
__device__ float g_pl[NS * BB * TT];

__device__ __forceinline__ void mma_f16(float* c, const uint32_t* a, uint32_t b0, uint32_t b1) {
    asm volatile(
        "mma.sync.aligned.m16n8k16.row.col.f32.f16.f16.f32 "
        "{%0,%1,%2,%3}, {%4,%5,%6,%7}, {%8,%9}, {%0,%1,%2,%3};"
        : "+f"(c[0]), "+f"(c[1]), "+f"(c[2]), "+f"(c[3])
        : "r"(a[0]), "r"(a[1]), "r"(a[2]), "r"(a[3]), "r"(b0), "r"(b1));
}
__device__ __forceinline__ uint32_t packh2(float x, float y) {
    __half2 h = __floats2half2_rn(x, y);
    return *(uint32_t*)&h;
}
__device__ __forceinline__ uint32_t hex2x2(uint32_t x) {
    uint32_t r; asm("ex2.approx.f16x2 %0, %1;" : "=r"(r) : "r"(x)); return r;
}
__device__ __forceinline__ uint32_t smem_u32(const void* p) {
    uint32_t a;
    asm("{ .reg .u64 t; cvta.to.shared.u64 t, %1; cvt.u32.u64 %0, t; }"
        : "=r"(a) : "l"(p));
    return a;
}
__device__ __forceinline__ void ldmatrix_x4(uint32_t* r, uint32_t addr) {
    asm volatile("ldmatrix.sync.aligned.m8n8.x4.shared.b16 {%0,%1,%2,%3}, [%4];"
        : "=r"(r[0]), "=r"(r[1]), "=r"(r[2]), "=r"(r[3]) : "r"(addr));
}
__device__ __forceinline__ void ldmatrix_x4t(uint32_t* r, uint32_t addr) {
    asm volatile("ldmatrix.sync.aligned.m8n8.x4.trans.shared.b16 {%0,%1,%2,%3}, [%4];"
        : "=r"(r[0]), "=r"(r[1]), "=r"(r[2]), "=r"(r[3]) : "r"(addr));
}
__device__ __forceinline__ void ldmatrix_x2(uint32_t& r0, uint32_t& r1, uint32_t addr) {
    asm volatile("ldmatrix.sync.aligned.m8n8.x2.shared.b16 {%0,%1}, [%2];"
        : "=r"(r0), "=r"(r1) : "r"(addr));
}
__device__ __forceinline__ float ex2f(float x) {
    float r; asm("ex2.approx.ftz.f32 %0, %1;" : "=f"(r) : "f"(x)); return r;
}
#define CP_ASYNC16(dst, src) \
    asm volatile("cp.async.cg.shared.global [%0], [%1], 16;" :: "r"(dst), "l"(src))
#define CP_COMMIT() asm volatile("cp.async.commit_group;" ::: "memory")
#define CP_WAIT0()  asm volatile("cp.async.wait_group 0;" ::: "memory")

// ---------------------------------------------------------------------------
// Prep: fused transposed weights Wt[n=192][k=768] as half.
// ---------------------------------------------------------------------------
__global__ __launch_bounds__(256) void wt_kernel(
    const float* __restrict__ Wq,
    const float* __restrict__ Wk,
    const float* __restrict__ Wv)
{
    int i = blockIdx.x * 256 + threadIdx.x;
    int n = i / CC;
    int k = i - n * CC;
    const float* W = (n < 64) ? Wq : (n < 128) ? Wk : Wv;
    g_wth[i] = __float2half_rn(W[k * HH + (n & 63)]);
}

// ---------------------------------------------------------------------------
// QKV via fp16 mma.sync, software-pipelined staging (proven R11).
// ---------------------------------------------------------------------------
__global__ __launch_bounds__(256) void qkv_mma_kernel(const float* __restrict__ x)
{
    __shared__ __half As[2][32][40];
    __shared__ __half Bs[2][192][40];
    const uint32_t ABUF = 32 * 40 * 2;
    const uint32_t BBUF = 192 * 40 * 2;

    int tid = threadIdx.x;
    int wid = tid >> 5, lane = tid & 31;
    int g   = lane >> 2, tig = lane & 3;
    int mw  = wid >> 2, nw = wid & 3;
    int mt  = blockIdx.x;

    float acc[6][4];
#pragma unroll
    for (int t = 0; t < 6; ++t)
#pragma unroll
        for (int j = 0; j < 4; ++j) acc[t][j] = 0.f;

    uint32_t addrA = smem_u32(&As[0][(mw << 4) + (lane & 15)][(lane >> 4) << 3]);
    uint32_t addrB = smem_u32(&Bs[0][nw * 48 + (lane & 7)][((lane >> 3) & 1) << 3]);

    int ar  = tid >> 3;
    int akq = (tid & 7) << 2;
    const float* xrow = x + (size_t)(mt * 32 + ar) * CC + akq;

    float4 va = *(const float4*)xrow;
    uint4 vb[3];
#pragma unroll
    for (int j = 0; j < 3; ++j) {
        int u = tid + j * 256;
        int n = u >> 2, k8 = (u & 3) << 3;
        vb[j] = *(const uint4*)&g_wth[(size_t)n * CC + k8];
    }

    for (int it = 0; it < CC / 32; ++it) {
        int buf = it & 1;
        *(uint2*)&As[buf][ar][akq] = make_uint2(packh2(va.x, va.y), packh2(va.z, va.w));
#pragma unroll
        for (int j = 0; j < 3; ++j) {
            int u = tid + j * 256;
            int n = u >> 2, k8 = (u & 3) << 3;
            *(uint4*)&Bs[buf][n][k8] = vb[j];
        }
        __syncthreads();

        if (it + 1 < CC / 32) {
            int ck = (it + 1) * 32;
            va = *(const float4*)(xrow + ck);
#pragma unroll
            for (int j = 0; j < 3; ++j) {
                int u = tid + j * 256;
                int n = u >> 2, k8 = (u & 3) << 3;
                vb[j] = *(const uint4*)&g_wth[(size_t)n * CC + ck + k8];
            }
        }

        uint32_t aA = addrA + buf * ABUF;
        uint32_t aB = addrB + buf * BBUF;
#pragma unroll
        for (int ks = 0; ks < 2; ++ks) {
            uint32_t a[4];
            ldmatrix_x4(a, aA + ks * 32);
#pragma unroll
            for (int t = 0; t < 6; ++t) {
                uint32_t b0, b1;
                ldmatrix_x2(b0, b1, aB + t * (8 * 80) + ks * 32);
                mma_f16(acc[t], a, b0, b1);
            }
        }
    }

    int row0 = mt * 32 + (mw << 4) + g;
#pragma unroll
    for (int t = 0; t < 6; ++t) {
        int n0  = nw * 48 + t * 8;
        __half* G = (n0 < 64) ? g_qh : (n0 < 128) ? g_kh : g_vh;
        int ncol = (n0 & 63) + (tig << 1);
        *(uint32_t*)&G[(size_t)row0 * HH + ncol] = packh2(acc[t][0], acc[t][1]);
        *(uint32_t*)&G[(size_t)(row0 + 8) * HH + ncol] = packh2(acc[t][2], acc[t][3]);
    }
}

// ---------------------------------------------------------------------------
// Flash attention: fp16 mma, cp.async double-buffer, x4 ldmatrix B-frags,
// f16x2 exp2 softmax. kv-split x4, fp16 partials.
// ---------------------------------------------------------------------------
__global__ __launch_bounds__(256, 2) void attn_mma_kernel()
{
    int blk = blockIdx.x;
    int s   = blk & 3;
    int b   = (blk >> 2) & 3;
    int qt  = 15 - (blk >> 4);
    int tid = threadIdx.x;
    int wid = tid >> 5, lane = tid & 31;
    int g   = lane >> 2, tig = lane & 3;

    int nkt = 2 * qt + 2;
    int t0  = (s * nkt) >> 2;
    int t1  = ((s + 1) * nkt) >> 2;

    __half* po = g_poh + ((size_t)(s * BB + b) * TT + qt * BQM) * HH;
    float* pm = g_pm + (size_t)(s * BB + b) * TT + qt * BQM;
    float* pl = g_pl + (size_t)(s * BB + b) * TT + qt * BQM;

    if (t0 == t1) {
        for (int i = tid; i < (BQM * HH) / 2; i += 256) ((uint32_t*)po)[i] = 0;
        if (tid < BQM) { pm[tid] = -CUDART_INF_F; pl[tid] = 0.f; }
        return;
    }

    __shared__ __half Qh[128][72];
    __shared__ __half Kh[2][64][72];
    __shared__ __half Vh[2][64][72];

    {
        const __half* qsrc = g_qh + (size_t)(b * TT + qt * BQM) * HH;
#pragma unroll
        for (int i = 0; i < 4; ++i) {
            int u = tid + i * 256;
            int r = u >> 3, c = (u & 7) << 3;
            CP_ASYNC16(smem_u32(&Qh[r][c]), qsrc + (size_t)r * HH + c);
        }
        const __half* ks = g_kh + (size_t)(b * TT + t0 * BKN) * HH;
        const __half* vs = g_vh + (size_t)(b * TT + t0 * BKN) * HH;
#pragma unroll
        for (int i = 0; i < 2; ++i) {
            int u = tid + i * 256;
            int r = u >> 3, c = (u & 7) << 3;
            CP_ASYNC16(smem_u32(&Kh[0][r][c]), ks + (size_t)r * HH + c);
            CP_ASYNC16(smem_u32(&Vh[0][r][c]), vs + (size_t)r * HH + c);
        }
        CP_COMMIT();
        CP_WAIT0();
    }
    __syncthreads();

    uint32_t aq[4][4];
    {
        uint32_t addrQ = smem_u32(&Qh[wid * 16 + (lane & 15)][(lane >> 4) << 3]);
#pragma unroll
        for (int ks = 0; ks < 4; ++ks)
            ldmatrix_x4(aq[ks], addrQ + ks * 32);
    }

    // x4 fragment bases: K serves nt-pairs, V (trans) serves ht-pairs
    uint32_t aKb = smem_u32(&Kh[0][(lane & 7) + ((lane >> 4) << 3)][((lane >> 3) & 1) << 3]);
    uint32_t aVb = smem_u32(&Vh[0][lane & 15][(lane >> 4) << 3]);
    const uint32_t bufstride = 64 * 72 * 2;

    float oc[8][4];
#pragma unroll
    for (int ht = 0; ht < 8; ++ht)
#pragma unroll
        for (int j = 0; j < 4; ++j) oc[ht][j] = 0.f;
    float m0 = -CUDART_INF_F, m1 = -CUDART_INF_F, l0 = 0.f, l1 = 0.f;

    int qrow0 = qt * BQM + wid * 16 + g;
    const float SCL2 = 0.125f * 1.4426950408889634f;

    int buf = 0;
    for (int kt = t0; kt < t1; ++kt) {
        if (kt + 1 < t1) {
            const __half* ks = g_kh + (size_t)(b * TT + (kt + 1) * BKN) * HH;
            const __half* vs = g_vh + (size_t)(b * TT + (kt + 1) * BKN) * HH;
            int nb = buf ^ 1;
#pragma unroll
            for (int i = 0; i < 2; ++i) {
                int u = tid + i * 256;
                int r = u >> 3, c = (u & 7) << 3;
                CP_ASYNC16(smem_u32(&Kh[nb][r][c]), ks + (size_t)r * HH + c);
                CP_ASYNC16(smem_u32(&Vh[nb][r][c]), vs + (size_t)r * HH + c);
            }
            CP_COMMIT();
        }

        uint32_t addrK = aKb + buf * bufstride;
        uint32_t addrV = aVb + buf * bufstride;

        // S = Q K^T (x4 B-frags: two nt per ldmatrix)
        float c[8][4];
#pragma unroll
        for (int ntp = 0; ntp < 4; ++ntp) {
            c[2 * ntp][0] = c[2 * ntp][1] = c[2 * ntp][2] = c[2 * ntp][3] = 0.f;
            c[2 * ntp + 1][0] = c[2 * ntp + 1][1] = c[2 * ntp + 1][2] = c[2 * ntp + 1][3] = 0.f;
#pragma unroll
            for (int ks = 0; ks < 4; ++ks) {
                uint32_t r[4];
                ldmatrix_x4(r, addrK + ntp * (16 * 144) + ks * 32);
                mma_f16(c[2 * ntp],     aq[ks], r[0], r[1]);
                mma_f16(c[2 * ntp + 1], aq[ks], r[2], r[3]);
            }
        }

        bool needmask = (kt * BKN + 63 > qt * BQM);
#pragma unroll
        for (int nt = 0; nt < 8; ++nt) {
            int kc = kt * BKN + nt * 8 + 2 * tig;
#pragma unroll
            for (int j = 0; j < 4; ++j) {
                c[nt][j] *= SCL2;
                if (needmask) {
                    int kg = kc + (j & 1);
                    int qg = (j < 2) ? qrow0 : qrow0 + 8;
                    if (kg > qg) c[nt][j] = -CUDART_INF_F;
                }
            }
        }

        float rm0 = -CUDART_INF_F, rm1 = -CUDART_INF_F;
#pragma unroll
        for (int nt = 0; nt < 8; ++nt) {
            rm0 = fmaxf(rm0, fmaxf(c[nt][0], c[nt][1]));
            rm1 = fmaxf(rm1, fmaxf(c[nt][2], c[nt][3]));
        }
        rm0 = fmaxf(rm0, __shfl_xor_sync(0xffffffff, rm0, 1));
        rm0 = fmaxf(rm0, __shfl_xor_sync(0xffffffff, rm0, 2));
        rm1 = fmaxf(rm1, __shfl_xor_sync(0xffffffff, rm1, 1));
        rm1 = fmaxf(rm1, __shfl_xor_sync(0xffffffff, rm1, 2));

        float mn0 = fmaxf(m0, rm0), mn1 = fmaxf(m1, rm1);
        float mb0 = (mn0 == -CUDART_INF_F) ? 0.f : mn0;
        float mb1 = (mn1 == -CUDART_INF_F) ? 0.f : mn1;
        float corr0 = ex2f(m0 - mb0);
        float corr1 = ex2f(m1 - mb1);
        m0 = mn0; m1 = mn1;

        // f16x2 exp2: ph[nt][0] = p(row g pair), ph[nt][1] = p(row g+8 pair)
        // ph[2kk..2kk+1] is exactly the PV A-frag for k-step kk.
        uint32_t ph[8][2];
        float rs0 = 0.f, rs1 = 0.f;
#pragma unroll
        for (int nt = 0; nt < 8; ++nt) {
            ph[nt][0] = hex2x2(packh2(c[nt][0] - mb0, c[nt][1] - mb0));
            ph[nt][1] = hex2x2(packh2(c[nt][2] - mb1, c[nt][3] - mb1));
            float2 f0 = __half22float2(*(const __half2*)&ph[nt][0]);
            float2 f1 = __half22float2(*(const __half2*)&ph[nt][1]);
            rs0 += f0.x + f0.y;
            rs1 += f1.x + f1.y;
        }
        rs0 += __shfl_xor_sync(0xffffffff, rs0, 1);
        rs0 += __shfl_xor_sync(0xffffffff, rs0, 2);
        rs1 += __shfl_xor_sync(0xffffffff, rs1, 1);
        rs1 += __shfl_xor_sync(0xffffffff, rs1, 2);
        l0 = l0 * corr0 + rs0;
        l1 = l1 * corr1 + rs1;

        // O rescale + PV mma (x4 trans: two ht per ldmatrix)
#pragma unroll
        for (int ht = 0; ht < 8; ++ht) {
            oc[ht][0] *= corr0; oc[ht][1] *= corr0;
            oc[ht][2] *= corr1; oc[ht][3] *= corr1;
        }
#pragma unroll
        for (int kk = 0; kk < 4; ++kk) {
            const uint32_t* pa = &ph[2 * kk][0];
#pragma unroll
            for (int htp = 0; htp < 4; ++htp) {
                uint32_t r[4];
                ldmatrix_x4t(r, addrV + kk * (16 * 144) + htp * 32);
                mma_f16(oc[2 * htp],     pa, r[0], r[1]);
                mma_f16(oc[2 * htp + 1], pa, r[2], r[3]);
            }
        }

        if (kt + 1 < t1) CP_WAIT0();
        __syncthreads();
        buf ^= 1;
    }

    int r0 = wid * 16 + g;
    int r1 = r0 + 8;
#pragma unroll
    for (int ht = 0; ht < 8; ++ht) {
        int col = ht * 8 + 2 * tig;
        *(uint32_t*)&po[(size_t)r0 * HH + col] = packh2(oc[ht][0], oc[ht][1]);
        *(uint32_t*)&po[(size_t)r1 * HH + col] = packh2(oc[ht][2], oc[ht][3]);
    }
    if (tig == 0) {
        pm[r0] = m0; pl[r0] = l0;
        pm[r1] = m1; pl[r1] = l1;
    }
}

// ---------------------------------------------------------------------------
// Combine kv-split partials: 8 elements per thread (uint4 per split).
// ---------------------------------------------------------------------------
__global__ __launch_bounds__(256) void combine_kernel(float* __restrict__ out)
{
    int i8  = blockIdx.x * 256 + threadIdx.x;   // group of 8 elems, < 65536
    int row = i8 >> 3;
    int col = (i8 & 7) << 3;

    const int MS = BB * TT;
    const int PS = BB * TT * HH;

    float m0 = g_pm[row], m1 = g_pm[MS + row],
          m2 = g_pm[2 * MS + row], m3 = g_pm[3 * MS + row];
    float ms = fmaxf(fmaxf(m0, m1), fmaxf(m2, m3));
    float w0 = ex2f(m0 - ms), w1 = ex2f(m1 - ms);
    float w2 = ex2f(m2 - ms), w3 = ex2f(m3 - ms);
    float lt = w0 * g_pl[row] + w1 * g_pl[MS + row]
             + w2 * g_pl[2 * MS + row] + w3 * g_pl[3 * MS + row];
    float inv = 1.f / lt;

    float o[8] = {0.f, 0.f, 0.f, 0.f, 0.f, 0.f, 0.f, 0.f};
    float w[4] = {w0, w1, w2, w3};
    size_t base = (size_t)row * HH + col;
#pragma unroll
    for (int s = 0; s < 4; ++s) {
        uint4 u = *(const uint4*)&g_poh[(size_t)s * PS + base];
        float2 p0 = __half22float2(*(const __half2*)&u.x);
        float2 p1 = __half22float2(*(const __half2*)&u.y);
        float2 p2 = __half22float2(*(const __half2*)&u.z);
        float2 p3 = __half22float2(*(const __half2*)&u.w);
        o[0] += w[s] * p0.x; o[1] += w[s] * p0.y;
        o[2] += w[s] * p1.x; o[3] += w[s] * p1.y;
        o[4] += w[s] * p2.x; o[5] += w[s] * p2.y;
        o[6] += w[s] * p3.x; o[7] += w[s] * p3.y;
    }
    *(float4*)&out[base]     = make_float4(o[0] * inv, o[1] * inv, o[2] * inv, o[3] * inv);
    *(float4*)&out[base + 4] = make_float4(o[4] * inv, o[5] * inv, o[6] * inv, o[7] * inv);
}

extern "C" void kernel_launch(void* const* d_in, const int* in_sizes, int n_in,
                              void* d_out, int out_size)
{
    const float* x  = (const float*)d_in[0];
    const float* Wq = (const float*)d_in[1];
    const float* Wk = (const float*)d_in[2];
    const float* Wv = (const float*)d_in[3];
    float* out = (float*)d_out;

    wt_kernel<<<(3 * HH * CC) / 256, 256>>>(Wq, Wk, Wv);
    qkv_mma_kernel<<<(BB * TT) / 32, 256>>>(x);
    attn_mma_kernel<<<16 * 4 * NS, 256>>>();
    combine_kernel<<<(BB * TT * HH) / 8 / 256, 256>>>(out);
}